// round 15
// baseline (speedup 1.0000x reference)
#include <cuda_runtime.h>
#include <cstdint>

#define RR     128
#define LL     384
#define DDIM   128
#define HHEADS 8
#define DHEAD  64
#define DPAIR  128
#define INNERD 512
#define ML     (RR*LL)
#define DHW    16
#define LDW    1536
#define LDH    1664
#define LDC2   1024

// ---------------- scratch ----------
__device__ float g_Mt  [ML*DDIM];
__device__ float g_QKVW[ML*LDW];
__device__ float g_QKVH[ML*LDH];
__device__ float g_QW  [ML*INNERD];
__device__ float g_CWH [ML*LDC2];
__device__ float g_QS  [LL*DDIM];
__device__ float g_TIE  [HHEADS*RR*LL];
__device__ float g_DOTS [HHEADS*LL*LL];
__device__ float g_DOTS2[HHEADS*LL*LL];
__device__ float g_PB  [HHEADS*LL*LL];
__device__ float g_ATT [HHEADS*LL*LL];
__device__ float g_WtW [1536*DDIM];
__device__ float g_WtH [LDH*DDIM];
__device__ float g_WtO [DDIM*LDC2];
__device__ float g_WtSq[DDIM*DDIM];
__device__ float g_BH  [LDH];

// ---------------------------------------------------------------------------
__device__ __forceinline__ void mma_tf32(float* d, const uint32_t* a, const uint32_t* b) {
    asm volatile(
        "mma.sync.aligned.m16n8k8.row.col.f32.tf32.tf32.f32 "
        "{%0,%1,%2,%3}, {%4,%5,%6,%7}, {%8,%9}, {%0,%1,%2,%3};"
        : "+f"(d[0]), "+f"(d[1]), "+f"(d[2]), "+f"(d[3])
        : "r"(a[0]), "r"(a[1]), "r"(a[2]), "r"(a[3]), "r"(b[0]), "r"(b[1]));
}
__device__ __forceinline__ uint32_t f2tf32(float v) {
    uint32_t o;
    asm("cvt.rna.tf32.f32 %0, %1;" : "=r"(o) : "f"(v));
    return o;
}
__device__ __forceinline__ float tf32f(float v) {
    return __uint_as_float(f2tf32(v));
}
__device__ __forceinline__ uint32_t smem_u32(const void* p) {
    uint32_t a;
    asm("{ .reg .u64 t; cvta.to.shared.u64 t, %1; cvt.u32.u64 %0, t; }"
        : "=r"(a) : "l"(p));
    return a;
}
__device__ __forceinline__ void cp16(uint32_t dst, const void* src) {
    asm volatile("cp.async.ca.shared.global [%0], [%1], 16;" :: "r"(dst), "l"(src));
}
__device__ __forceinline__ void pipe_wait(bool more) {
    if (more) asm volatile("cp.async.wait_group 1;");
    else      asm volatile("cp.async.wait_group 0;");
}
// A-fragment (16x8 tf32) via ldmatrix.x4
__device__ __forceinline__ void ldsmA(uint32_t* af, uint32_t base, int strw,
                                      int rw, int ks, int lane) {
    int j = lane & 7, sel = lane >> 3;
    uint32_t addr = base + (uint32_t)(((rw + (sel & 1) * 8 + j) * strw
                                       + ks + (sel >> 1) * 4) << 2);
    asm volatile("ldmatrix.sync.aligned.m8n8.x4.shared.b16 {%0,%1,%2,%3}, [%4];"
        : "=r"(af[0]), "=r"(af[1]), "=r"(af[2]), "=r"(af[3]) : "r"(addr));
}
// B fragments for TWO adjacent 8-col tiles via one ldmatrix.x4:
// bf[0..1] = frag rows n0..n0+7, bf[2..3] = frag rows n0+8..n0+15
__device__ __forceinline__ void ldsmB4(uint32_t* bf, uint32_t base, int strw,
                                       int n0, int ks, int lane) {
    int j = lane & 7, g = lane >> 3;
    uint32_t addr = base + (uint32_t)(((n0 + (g >> 1) * 8 + j) * strw
                                       + ks + (g & 1) * 4) << 2);
    asm volatile("ldmatrix.sync.aligned.m8n8.x4.shared.b16 {%0,%1,%2,%3}, [%4];"
        : "=r"(bf[0]), "=r"(bf[1]), "=r"(bf[2]), "=r"(bf[3]) : "r"(addr));
}
// single B fragment (x2) kept for odd cases
__device__ __forceinline__ void ldsmB(uint32_t* bf, uint32_t base, int strw,
                                      int n0, int ks, int lane) {
    int j = lane & 7, sel = (lane >> 3) & 1;
    uint32_t addr = base + (uint32_t)(((n0 + j) * strw + ks + sel * 4) << 2);
    asm volatile("ldmatrix.sync.aligned.m8n8.x2.shared.b16 {%0,%1}, [%2];"
        : "=r"(bf[0]), "=r"(bf[1]) : "r"(addr));
}

// ---------------------------------------------------------------------------
__global__ __launch_bounds__(256) void cvt_k(const float* __restrict__ s,
                                             float* __restrict__ d)
{
    int i = (blockIdx.x * 256 + threadIdx.x) * 4;
    float4 v = *(const float4*)&s[i];
    v.x = tf32f(v.x); v.y = tf32f(v.y); v.z = tf32f(v.z); v.w = tf32f(v.w);
    *(float4*)&d[i] = v;
}

__global__ void biasext_k(const float* __restrict__ bsk, float* __restrict__ be)
{
    int i = blockIdx.x * 256 + threadIdx.x;
    if (i < LDH) be[i] = (i >= 1536) ? bsk[i - 1536] : 0.f;
}

__global__ __launch_bounds__(128) void scaleq_k(
    const float* __restrict__ TIE, const float* __restrict__ QKVH,
    float* __restrict__ QW)
{
    const int i = blockIdx.x;
    const int r = blockIdx.y;
    const int t = threadIdx.x;
    const int h = t >> 4;
    const size_t row = (size_t)r * LL + i;
    float wv = TIE[((size_t)h * RR + r) * LL + i];
    float4 v = *(const float4*)&QKVH[row * LDH + t * 4];
    v.x = tf32f(v.x * wv); v.y = tf32f(v.y * wv);
    v.z = tf32f(v.z * wv); v.w = tf32f(v.w * wv);
    *(float4*)&QW[row * INNERD + t * 4] = v;
}

// ---------------------------------------------------------------------------
__global__ void transpose_k(const float* __restrict__ W, float* __restrict__ Wt,
                            int N, int ldt)
{
    __shared__ float tile[32][33];
    int kb = blockIdx.y * 32, nb = blockIdx.x * 32;
    int tx = threadIdx.x, ty = threadIdx.y;
#pragma unroll
    for (int i = 0; i < 32; i += 8)
        tile[ty + i][tx] = W[(size_t)(kb + ty + i) * N + nb + tx];
    __syncthreads();
#pragma unroll
    for (int i = 0; i < 32; i += 8)
        Wt[(size_t)(nb + ty + i) * ldt + kb + tx] = tf32f(tile[tx][ty + i]);
}

// ---------------------------------------------------------------------------
// tf32 GEMM, 3-stage cp.async pipeline, x4 B-fragment loads.
// ---------------------------------------------------------------------------
#define GEMM_SMEM (6 * 2560 * 4)
__global__ __launch_bounds__(256) void gemm_tc(
    const float* __restrict__ X, int ldx,
    const float* __restrict__ Wt, int ldw,
    const float* __restrict__ b1, const float* __restrict__ b2,
    float* __restrict__ C, int ldc,
    int K, float alpha)
{
    extern __shared__ float smg[];
    const int t    = threadIdx.x;
    const int lane = t & 31;
    const int wid  = t >> 5;
    const int wm   = (wid & 3) * 32;
    const int wn   = (wid >> 2) * 64;
    const int row0 = blockIdx.y * 128;
    const int col0 = blockIdx.x * 128;
    const int lr = t >> 2;
    const int lc = (t & 3) * 4;
    const uint32_t base = smem_u32(smg);

    float acc[2][8][4];
#pragma unroll
    for (int mt = 0; mt < 2; mt++)
#pragma unroll
        for (int nt = 0; nt < 8; nt++)
#pragma unroll
            for (int i = 0; i < 4; i++) acc[mt][nt][i] = 0.f;

    auto issue = [&](int c) {
        int s = c % 3;
        int k0 = c << 4;
        uint32_t aS = base + (uint32_t)(s * 2560) * 4;
        uint32_t bS = base + (uint32_t)((3 + s) * 2560) * 4;
#pragma unroll
        for (int half = 0; half < 2; half++) {
            int r = lr + half * 64;
            cp16(aS + (uint32_t)(r * 20 + lc) * 4,
                 &X[(size_t)(row0 + r) * ldx + k0 + lc]);
            cp16(bS + (uint32_t)(r * 20 + lc) * 4,
                 &Wt[(size_t)(col0 + r) * ldw + k0 + lc]);
        }
        asm volatile("cp.async.commit_group;");
    };

    const int nc = K >> 4;
    issue(0);
    if (nc > 1) issue(1);
    for (int c = 0; c < nc; c++) {
        pipe_wait(c + 1 < nc);
        __syncthreads();
        if (c + 2 < nc) issue(c + 2);
        const int s = c % 3;
        const uint32_t aS = base + (uint32_t)(s * 2560) * 4;
        const uint32_t bS = base + (uint32_t)((3 + s) * 2560) * 4;
#pragma unroll
        for (int ks = 0; ks < 16; ks += 8) {
            uint32_t af[2][4];
            ldsmA(af[0], aS, 20, wm,      ks, lane);
            ldsmA(af[1], aS, 20, wm + 16, ks, lane);
#pragma unroll
            for (int nt = 0; nt < 8; nt += 2) {
                uint32_t bf[4];
                ldsmB4(bf, bS, 20, wn + nt * 8, ks, lane);
                mma_tf32(acc[0][nt],     af[0], bf);
                mma_tf32(acc[1][nt],     af[1], bf);
                mma_tf32(acc[0][nt + 1], af[0], bf + 2);
                mma_tf32(acc[1][nt + 1], af[1], bf + 2);
            }
        }
    }

#pragma unroll
    for (int mt = 0; mt < 2; mt++) {
#pragma unroll
        for (int nt = 0; nt < 8; nt++) {
            int rg = row0 + wm + mt * 16 + (lane >> 2);
            int cg = col0 + wn + nt * 8 + (lane & 3) * 2;
            float bx = 0.f, by = 0.f;
            if (b1) { bx += b1[cg]; by += b1[cg + 1]; }
            if (b2) { bx += b2[cg]; by += b2[cg + 1]; }
#pragma unroll
            for (int half = 0; half < 2; half++) {
                int r = rg + half * 8;
                float2 v = {alpha * (acc[mt][nt][half * 2 + 0] + bx),
                            alpha * (acc[mt][nt][half * 2 + 1] + by)};
                *(float2*)&C[(size_t)r * ldc + cg] = v;
            }
        }
    }
}

// ---------------------------------------------------------------------------
// dots_tc: pure GEMM over K=(r,d), x4 B loads, 3-stage pipeline.
// ---------------------------------------------------------------------------
#define DOTS_SMEM (6 * 4608 * 4)
__global__ __launch_bounds__(256) void dots_tc(
    const float* __restrict__ QW, const float* __restrict__ QKVH,
    float* __restrict__ D1, float* __restrict__ D2)
{
    extern __shared__ float smd[];
    const int t    = threadIdx.x;
    const int lane = t & 31;
    const int wid  = t >> 5;
    const int wm   = (wid & 3) * 32;
    const int wn   = (wid >> 2) * 64;
    const int i0 = blockIdx.y * 128;
    const int j0 = blockIdx.x * 128;
    const int h  = blockIdx.z & 7;
    const int rz = blockIdx.z >> 3;
    const int r00 = rz * 64;
    const uint32_t base = smem_u32(smd);

    float acc[2][8][4];
#pragma unroll
    for (int mt = 0; mt < 2; mt++)
#pragma unroll
        for (int nt = 0; nt < 8; nt++)
#pragma unroll
            for (int i = 0; i < 4; i++) acc[mt][nt][i] = 0.f;

    const int lr = t >> 1;
    const int lc = (t & 1) * 16;

    auto issue = [&](int c) {
        int s = c % 3;
        int r = r00 + (c >> 1);
        int d0 = (c & 1) * 32;
        uint32_t aS = base + (uint32_t)(s * 4608 + lr * 36 + lc) * 4;
        uint32_t bS = base + (uint32_t)((3 + s) * 4608 + lr * 36 + lc) * 4;
        const float* asrc = &QW[((size_t)r * LL + i0 + lr) * INNERD + h * DHEAD + d0 + lc];
        const float* bsrc = &QKVH[((size_t)r * LL + j0 + lr) * LDH + 512 + h * DHEAD + d0 + lc];
#pragma unroll
        for (int u = 0; u < 16; u += 4) {
            cp16(aS + u * 4, asrc + u);
            cp16(bS + u * 4, bsrc + u);
        }
        asm volatile("cp.async.commit_group;");
    };

    const int nc = 128;
    issue(0); issue(1);
    for (int c = 0; c < nc; c++) {
        pipe_wait(c + 1 < nc);
        __syncthreads();
        if (c + 2 < nc) issue(c + 2);
        const int s = c % 3;
        const uint32_t aS = base + (uint32_t)(s * 4608) * 4;
        const uint32_t bS = base + (uint32_t)((3 + s) * 4608) * 4;
#pragma unroll
        for (int ks = 0; ks < 32; ks += 8) {
            uint32_t af[2][4];
            ldsmA(af[0], aS, 36, wm,      ks, lane);
            ldsmA(af[1], aS, 36, wm + 16, ks, lane);
#pragma unroll
            for (int nt = 0; nt < 8; nt += 2) {
                uint32_t bf[4];
                ldsmB4(bf, bS, 36, wn + nt * 8, ks, lane);
                mma_tf32(acc[0][nt],     af[0], bf);
                mma_tf32(acc[1][nt],     af[1], bf);
                mma_tf32(acc[0][nt + 1], af[0], bf + 2);
                mma_tf32(acc[1][nt + 1], af[1], bf + 2);
            }
        }
    }

    float* OUT = (rz ? D2 : D1) + (size_t)h * LL * LL;
#pragma unroll
    for (int mt = 0; mt < 2; mt++) {
#pragma unroll
        for (int nt = 0; nt < 8; nt++) {
            int rg = i0 + wm + mt * 16 + (lane >> 2);
            int cg = j0 + wn + nt * 8 + (lane & 3) * 2;
#pragma unroll
            for (int half = 0; half < 2; half++) {
                int rw = rg + half * 8;
                float2 v = {0.125f * acc[mt][nt][half * 2 + 0],
                            0.125f * acc[mt][nt][half * 2 + 1]};
                *(float2*)&OUT[(size_t)rw * LL + cg] = v;
            }
        }
    }
}

// ---------------------------------------------------------------------------
// Tensor-core column attention, x4 B loads in both MMA loops.
// ---------------------------------------------------------------------------
__global__ __launch_bounds__(256, 2) void col_attn_tc(
    const float* __restrict__ QKV, float* __restrict__ CWH)
{
    extern __shared__ float sm[];
    float* Qs = sm;
    float* Ks = sm + 128 * 68;
    float* P  = sm;
    float* Vt = sm + 2 * 128 * 68;

    const int l = blockIdx.x >> 3;
    const int h = blockIdx.x & 7;
    const int t = threadIdx.x;
    const int lane = t & 31;
    const int wid  = t >> 5;
    const int wm   = wid * 16;
    const int fr   = lane >> 2;
    const int q2   = (lane & 3) * 2;
    const size_t RS = (size_t)LL * LDW;
    const uint32_t qsu = smem_u32(Qs);
    const uint32_t ksu = smem_u32(Ks);
    const uint32_t psu = smem_u32(P);
    const uint32_t vsu = smem_u32(Vt);

    const float* qb = QKV + (size_t)l * LDW + h * DHEAD;
    const float* kb = qb + 512;
    const float* vb = qb + 1024;

    for (int idx = t; idx < 2048; idx += 256) {
        int row = idx >> 4, c4 = (idx & 15) * 4;
        float4 a = *(const float4*)(qb + row * RS + c4);
        float4 b = *(const float4*)(kb + row * RS + c4);
        *(float4*)&Qs[row * 68 + c4] = a;
        *(float4*)&Ks[row * 68 + c4] = b;
    }
    __syncthreads();

    float acc[16][4];
#pragma unroll
    for (int nt = 0; nt < 16; nt++)
#pragma unroll
        for (int i = 0; i < 4; i++) acc[nt][i] = 0.f;

#pragma unroll
    for (int ks = 0; ks < 64; ks += 8) {
        uint32_t af[4];
        ldsmA(af, qsu, 68, wm, ks, lane);
#pragma unroll
        for (int nt = 0; nt < 16; nt += 2) {
            uint32_t bf[4];
            ldsmB4(bf, ksu, 68, nt * 8, ks, lane);
            mma_tf32(acc[nt],     af, bf);
            mma_tf32(acc[nt + 1], af, bf + 2);
        }
    }

    float mx0 = -1e30f, mx1 = -1e30f;
#pragma unroll
    for (int nt = 0; nt < 16; nt++) {
        mx0 = fmaxf(mx0, fmaxf(acc[nt][0], acc[nt][1]));
        mx1 = fmaxf(mx1, fmaxf(acc[nt][2], acc[nt][3]));
    }
    mx0 = fmaxf(mx0, __shfl_xor_sync(0xffffffffu, mx0, 1));
    mx0 = fmaxf(mx0, __shfl_xor_sync(0xffffffffu, mx0, 2));
    mx1 = fmaxf(mx1, __shfl_xor_sync(0xffffffffu, mx1, 1));
    mx1 = fmaxf(mx1, __shfl_xor_sync(0xffffffffu, mx1, 2));
    float s0 = 0.f, s1 = 0.f;
#pragma unroll
    for (int nt = 0; nt < 16; nt++) {
        acc[nt][0] = __expf(0.125f * (acc[nt][0] - mx0)); s0 += acc[nt][0];
        acc[nt][1] = __expf(0.125f * (acc[nt][1] - mx0)); s0 += acc[nt][1];
        acc[nt][2] = __expf(0.125f * (acc[nt][2] - mx1)); s1 += acc[nt][2];
        acc[nt][3] = __expf(0.125f * (acc[nt][3] - mx1)); s1 += acc[nt][3];
    }
    s0 += __shfl_xor_sync(0xffffffffu, s0, 1);
    s0 += __shfl_xor_sync(0xffffffffu, s0, 2);
    s1 += __shfl_xor_sync(0xffffffffu, s1, 1);
    s1 += __shfl_xor_sync(0xffffffffu, s1, 2);

    __syncthreads();

#pragma unroll
    for (int nt = 0; nt < 16; nt++) {
        float2 p0 = {tf32f(acc[nt][0]), tf32f(acc[nt][1])};
        float2 p1 = {tf32f(acc[nt][2]), tf32f(acc[nt][3])};
        *(float2*)&P[(wm + fr) * 132 + nt * 8 + q2]     = p0;
        *(float2*)&P[(wm + fr + 8) * 132 + nt * 8 + q2] = p1;
    }
    for (int idx = t; idx < 2048; idx += 256) {
        int j = idx >> 4, c4 = (idx & 15) * 4;
        float4 v = *(const float4*)(vb + j * RS + c4);
        Vt[(c4 + 0) * 132 + j] = v.x;
        Vt[(c4 + 1) * 132 + j] = v.y;
        Vt[(c4 + 2) * 132 + j] = v.z;
        Vt[(c4 + 3) * 132 + j] = v.w;
    }
    __syncthreads();

    float o[8][4];
#pragma unroll
    for (int nt = 0; nt < 8; nt++)
#pragma unroll
        for (int i = 0; i < 4; i++) o[nt][i] = 0.f;

#pragma unroll
    for (int ks = 0; ks < 128; ks += 8) {
        uint32_t af[4];
        ldsmA(af, psu, 132, wm, ks, lane);
#pragma unroll
        for (int nt = 0; nt < 8; nt += 2) {
            uint32_t bf[4];
            ldsmB4(bf, vsu, 132, nt * 8, ks, lane);
            mma_tf32(o[nt],     af, bf);
            mma_tf32(o[nt + 1], af, bf + 2);
        }
    }

    const float inv0 = 1.f / s0, inv1 = 1.f / s1;
    float* ow = CWH + (size_t)l * LDC2 + h * DHEAD;
    const size_t OS = (size_t)LL * LDC2;
#pragma unroll
    for (int nt = 0; nt < 8; nt++) {
        int cg = nt * 8 + q2;
        float2 v0 = {tf32f(o[nt][0] * inv0), tf32f(o[nt][1] * inv0)};
        float2 v1 = {tf32f(o[nt][2] * inv1), tf32f(o[nt][3] * inv1)};
        *(float2*)(ow + (size_t)(wm + fr) * OS + cg)     = v0;
        *(float2*)(ow + (size_t)(wm + fr + 8) * OS + cg) = v1;
    }
}

// ---------------------------------------------------------------------------
// oh_tc, x4 B loads.
// ---------------------------------------------------------------------------
__global__ __launch_bounds__(256) void oh_tc(
    const float* __restrict__ ATT, const float* __restrict__ QKV,
    float* __restrict__ CWH)
{
    __shared__ float As[128 * 20];
    __shared__ float Bs[64 * 20];

    const int t    = threadIdx.x;
    const int lane = t & 31;
    const int wid  = t >> 5;
    const int wm   = (wid & 3) * 32;
    const int wn   = (wid >> 2) * 32;
    const int i0 = blockIdx.x * 128;
    const int r  = blockIdx.y >> 3;
    const int h  = blockIdx.y & 7;
    const uint32_t asu = smem_u32(As);
    const uint32_t bsu = smem_u32(Bs);

    float acc[2][4][4];
#pragma unroll
    for (int mt = 0; mt < 2; mt++)
#pragma unroll
        for (int nt = 0; nt < 4; nt++)
#pragma unroll
            for (int i = 0; i < 4; i++) acc[mt][nt][i] = 0.f;

    for (int k0 = 0; k0 < LL; k0 += 16) {
#pragma unroll
        for (int i = 0; i < 2; i++) {
            int idx = t + 256 * i;
            int row = idx >> 2, c4 = (idx & 3) * 4;
            float4 va = *(const float4*)&ATT[((size_t)h * LL + i0 + row) * LL + k0 + c4];
            uint4 ua;
            ua.x = f2tf32(va.x); ua.y = f2tf32(va.y);
            ua.z = f2tf32(va.z); ua.w = f2tf32(va.w);
            *(uint4*)&As[row * 20 + c4] = ua;
        }
        {
            int kr = t >> 4;
            int dc = (t & 15) * 4;
            float4 vb = *(const float4*)&QKV[((size_t)(r * LL + k0 + kr)) * LDH + 1024 + h * DHEAD + dc];
            Bs[(dc + 0) * 20 + kr] = vb.x;
            Bs[(dc + 1) * 20 + kr] = vb.y;
            Bs[(dc + 2) * 20 + kr] = vb.z;
            Bs[(dc + 3) * 20 + kr] = vb.w;
        }
        __syncthreads();
#pragma unroll
        for (int ks = 0; ks < 16; ks += 8) {
            uint32_t af[2][4];
            ldsmA(af[0], asu, 20, wm,      ks, lane);
            ldsmA(af[1], asu, 20, wm + 16, ks, lane);
#pragma unroll
            for (int nt = 0; nt < 4; nt += 2) {
                uint32_t bf[4];
                ldsmB4(bf, bsu, 20, wn + nt * 8, ks, lane);
                mma_tf32(acc[0][nt],     af[0], bf);
                mma_tf32(acc[1][nt],     af[1], bf);
                mma_tf32(acc[0][nt + 1], af[0], bf + 2);
                mma_tf32(acc[1][nt + 1], af[1], bf + 2);
            }
        }
        __syncthreads();
    }

#pragma unroll
    for (int mt = 0; mt < 2; mt++) {
#pragma unroll
        for (int nt = 0; nt < 4; nt++) {
            int rloc = i0 + wm + mt * 16 + (lane >> 2);
            int cg   = wn + nt * 8 + (lane & 3) * 2;
#pragma unroll
            for (int half = 0; half < 2; half++) {
                int rw = rloc + half * 8;
                float2 v = {tf32f(acc[mt][nt][half * 2 + 0]),
                            tf32f(acc[mt][nt][half * 2 + 1])};
                *(float2*)&CWH[((size_t)(r * LL + rw)) * LDC2 + 512 + h * DHEAD + cg] = v;
            }
        }
    }
}

// ---------------------------------------------------------------------------
__global__ __launch_bounds__(128) void tie_k(
    const float* __restrict__ QS, const float* __restrict__ QKV,
    float* __restrict__ TIE)
{
    const int l = blockIdx.x >> 3;
    const int h = blockIdx.x & 7;
    const int r = threadIdx.x;
    const float* q = &QS[l * DDIM + h * DHW];
    const float* k = &QKV[((size_t)r * LL + l) * LDH + 1536 + h * DHW];
    float s = 0.f;
#pragma unroll
    for (int d = 0; d < DHW; d++) s += q[d] * k[d];
    s *= 0.25f;

    __shared__ float red[128];
    red[r] = s; __syncthreads();
    for (int o = 64; o; o >>= 1) { if (r < o) red[r] = fmaxf(red[r], red[r + o]); __syncthreads(); }
    float m = red[0]; __syncthreads();
    float e = __expf(s - m);
    red[r] = e; __syncthreads();
    for (int o = 64; o; o >>= 1) { if (r < o) red[r] += red[r + o]; __syncthreads(); }
    TIE[((size_t)h * RR + r) * LL + l] = e / red[0];
}

// ---------------------------------------------------------------------------
__global__ __launch_bounds__(128) void pb_k(
    const float* __restrict__ pair, const float* __restrict__ gam,
    const float* __restrict__ bet, const float* __restrict__ Wp,
    float* __restrict__ PB)
{
    const int w    = threadIdx.x >> 5;
    const int lane = threadIdx.x & 31;
    const int pid  = blockIdx.x * 4 + w;
    float4 x4 = *(const float4*)&pair[(size_t)pid * DPAIR + lane * 4];
    float x[4] = {x4.x, x4.y, x4.z, x4.w};
    float s1 = x[0] + x[1] + x[2] + x[3];
    float s2 = x[0]*x[0] + x[1]*x[1] + x[2]*x[2] + x[3]*x[3];
#pragma unroll
    for (int o = 16; o; o >>= 1) {
        s1 += __shfl_xor_sync(0xffffffffu, s1, o);
        s2 += __shfl_xor_sync(0xffffffffu, s2, o);
    }
    float mu  = s1 * (1.f / DPAIR);
    float var = s2 * (1.f / DPAIR) - mu * mu;
    float inv = rsqrtf(var + 1e-5f);

    float acc[8];
#pragma unroll
    for (int hh = 0; hh < 8; hh++) acc[hh] = 0.f;
#pragma unroll
    for (int u = 0; u < 4; u++) {
        int c = lane * 4 + u;
        float nx = (x[u] - mu) * inv * gam[c] + bet[c];
#pragma unroll
        for (int hh = 0; hh < 8; hh++) acc[hh] += nx * Wp[c * 8 + hh];
    }
#pragma unroll
    for (int o = 16; o; o >>= 1)
#pragma unroll
        for (int hh = 0; hh < 8; hh++) acc[hh] += __shfl_xor_sync(0xffffffffu, acc[hh], o);
    if (lane == 0) {
#pragma unroll
        for (int hh = 0; hh < 8; hh++) PB[(size_t)hh * LL * LL + pid] = acc[hh];
    }
}

// ---------------------------------------------------------------------------
__global__ __launch_bounds__(128) void softh_k(
    const float* __restrict__ D1, const float* __restrict__ D2,
    const float* __restrict__ PB, float* __restrict__ ATT)
{
    const int i = blockIdx.x;
    const int h = blockIdx.y;
    const int t = threadIdx.x;
    const size_t base = ((size_t)h * LL + i) * LL;
    const float* dp1 = D1 + base;
    const float* dp2 = D2 + base;
    const float* pb  = PB + base;
    float x[3];
#pragma unroll
    for (int u = 0; u < 3; u++) {
        int j = t + u * 128;
        x[u] = dp1[j] + dp2[j] + pb[j];
    }
    __shared__ float red[128];
    float lm = fmaxf(fmaxf(x[0], x[1]), x[2]);
    red[t] = lm; __syncthreads();
    for (int o = 64; o; o >>= 1) { if (t < o) red[t] = fmaxf(red[t], red[t + o]); __syncthreads(); }
    float mx = red[0]; __syncthreads();
    float e[3], ls = 0.f;
#pragma unroll
    for (int u = 0; u < 3; u++) { e[u] = __expf(x[u] - mx); ls += e[u]; }
    red[t] = ls; __syncthreads();
    for (int o = 64; o; o >>= 1) { if (t < o) red[t] += red[t + o]; __syncthreads(); }
    float inv = 1.f / red[0];
    float* ap = ATT + base;
#pragma unroll
    for (int u = 0; u < 3; u++) ap[t + u * 128] = e[u] * inv;
}

// ---------------------------------------------------------------------------
static float* sym(const void* s) {
    void* p = nullptr;
    cudaGetSymbolAddress(&p, s);
    return (float*)p;
}

extern "C" void kernel_launch(void* const* d_in, const int* in_sizes, int n_in,
                              void* d_out, int out_size)
{
    const float* m     = (const float*)d_in[0];
    const float* pair  = (const float*)d_in[1];
    const float* Wq_w  = (const float*)d_in[2];
    const float* Wkv_w = (const float*)d_in[3];
    const float* Wo_w  = (const float*)d_in[4];
    const float* bo_w  = (const float*)d_in[5];
    const float* Wq_h  = (const float*)d_in[6];
    const float* Wkv_h = (const float*)d_in[7];
    const float* Wo_h  = (const float*)d_in[8];
    const float* bo_h  = (const float*)d_in[9];
    const float* ln_g  = (const float*)d_in[10];
    const float* ln_b  = (const float*)d_in[11];
    const float* Wpair = (const float*)d_in[12];
    const float* Wsq   = (const float*)d_in[13];
    const float* bsq   = (const float*)d_in[14];
    const float* Wsk   = (const float*)d_in[15];
    const float* bsk   = (const float*)d_in[16];
    float* out = (float*)d_out;

    float* Mt    = sym(g_Mt);
    float* QKVW  = sym(g_QKVW);
    float* QKVH  = sym(g_QKVH);
    float* QW    = sym(g_QW);
    float* CWH   = sym(g_CWH);
    float* QS    = sym(g_QS);
    float* TIE   = sym(g_TIE);
    float* DOTS  = sym(g_DOTS);
    float* DOTS2 = sym(g_DOTS2);
    float* PB    = sym(g_PB);
    float* ATT   = sym(g_ATT);
    float* WtW   = sym(g_WtW);
    float* WtH   = sym(g_WtH);
    float* WtO   = sym(g_WtO);
    float* WtSq  = sym(g_WtSq);
    float* BH    = sym(g_BH);

    const int CA_SMEM = (2 * 128 * 68 + 64 * 132) * 4;
    cudaFuncSetAttribute(col_attn_tc, cudaFuncAttributeMaxDynamicSharedMemorySize, CA_SMEM);
    cudaFuncSetAttribute(gemm_tc, cudaFuncAttributeMaxDynamicSharedMemorySize, GEMM_SMEM);
    cudaFuncSetAttribute(dots_tc, cudaFuncAttributeMaxDynamicSharedMemorySize, DOTS_SMEM);

    static cudaStream_t sB = nullptr, sC = nullptr;
    static cudaEvent_t evMt, evPB, evB, evC;
    if (sB == nullptr) {
        cudaStreamCreateWithFlags(&sB, cudaStreamNonBlocking);
        cudaStreamCreateWithFlags(&sC, cudaStreamNonBlocking);
        cudaEventCreateWithFlags(&evMt, cudaEventDisableTiming);
        cudaEventCreateWithFlags(&evPB, cudaEventDisableTiming);
        cudaEventCreateWithFlags(&evB,  cudaEventDisableTiming);
        cudaEventCreateWithFlags(&evC,  cudaEventDisableTiming);
    }

    const dim3 tb(32, 8);

    // ---- stream 0: width path (#4 = ncu capture slot = width GEMM) ----
    cvt_k<<<ML * DDIM / 1024, 256>>>(m, Mt);                                   // #1
    cudaEventRecord(evMt, 0);
    transpose_k<<<dim3(16, 4), tb>>>(Wq_w,  WtW,              INNERD,     DDIM); // #2
    transpose_k<<<dim3(32, 4), tb>>>(Wkv_w, WtW + 512 * DDIM, 2 * INNERD, DDIM); // #3
    gemm_tc<<<dim3(12, 384), 256, GEMM_SMEM>>>(Mt, DDIM, WtW, DDIM, nullptr, nullptr,
                                               QKVW, LDW, DDIM, 1.f);          // #4
    col_attn_tc<<<LL * HHEADS, 256, CA_SMEM>>>(QKVW, CWH);                     // #5

    // ---- stream B: height path ----
    cudaStreamWaitEvent(sB, evMt, 0);
    transpose_k<<<dim3(16, 4), tb, 0, sB>>>(Wq_h,  WtH,               INNERD,     DDIM);
    transpose_k<<<dim3(32, 4), tb, 0, sB>>>(Wkv_h, WtH + 512 * DDIM,  2 * INNERD, DDIM);
    transpose_k<<<dim3(4, 4),  tb, 0, sB>>>(Wsk,   WtH + 1536 * DDIM, DDIM,       DDIM);
    transpose_k<<<dim3(4, 4),  tb, 0, sB>>>(Wsq,   WtSq,              DDIM,       DDIM);
    biasext_k<<<(LDH + 255) / 256, 256, 0, sB>>>(bsk, BH);
    gemm_tc<<<dim3(13, 384), 256, GEMM_SMEM, sB>>>(Mt, DDIM, WtH, DDIM, BH, nullptr,
                                                   QKVH, LDH, DDIM, 1.f);
    gemm_tc<<<dim3(1, 3), 256, GEMM_SMEM, sB>>>(Mt, DDIM, WtSq, DDIM, bsq, nullptr,
                                                QS, DDIM, DDIM, 1.f);
    tie_k<<<LL * HHEADS, 128, 0, sB>>>(QS, QKVH, TIE);
    scaleq_k<<<dim3(LL, RR), 128, 0, sB>>>(TIE, QKVH, QW);
    dots_tc<<<dim3(3, 3, 16), 256, DOTS_SMEM, sB>>>(QW, QKVH, DOTS, DOTS2);

    // ---- stream C: pair bias + output-weight prep ----
    cudaStreamWaitEvent(sC, evMt, 0);
    pb_k<<<LL * LL / 4, 128, 0, sC>>>(pair, ln_g, ln_b, Wpair, PB);
    cudaEventRecord(evPB, sC);
    transpose_k<<<dim3(4, 16), tb, 0, sC>>>(Wo_w, WtO,       DDIM, LDC2);
    transpose_k<<<dim3(4, 16), tb, 0, sC>>>(Wo_h, WtO + 512, DDIM, LDC2);
    cudaEventRecord(evC, sC);

    // ---- stream B tail ----
    cudaStreamWaitEvent(sB, evPB, 0);
    softh_k<<<dim3(LL, HHEADS), 128, 0, sB>>>(DOTS, DOTS2, PB, ATT);
    oh_tc<<<dim3(3, RR * HHEADS), 256, 0, sB>>>(ATT, QKVH, CWH);
    cudaEventRecord(evB, sB);

    // ---- join: fused output GEMM ----
    cudaStreamWaitEvent(0, evB, 0);
    cudaStreamWaitEvent(0, evC, 0);
    gemm_tc<<<dim3(1, 384), 256, GEMM_SMEM>>>(CWH, LDC2, WtO, LDC2, bo_w, bo_h,
                                              out, DDIM, LDC2, 0.5f);
}

// round 16
// speedup vs baseline: 1.0449x; 1.0449x over previous
#include <cuda_runtime.h>
#include <cstdint>

#define RR     128
#define LL     384
#define DDIM   128
#define HHEADS 8
#define DHEAD  64
#define DPAIR  128
#define INNERD 512
#define ML     (RR*LL)
#define DHW    16
#define LDW    1536
#define LDH    1664
#define LDC2   1024

// ---------------- scratch ----------
__device__ float g_Mt  [ML*DDIM];
__device__ float g_QKVW[ML*LDW];
__device__ float g_QKVH[ML*LDH];
__device__ float g_QW  [ML*INNERD];
__device__ float g_CWH [ML*LDC2];
__device__ float g_QS  [LL*DDIM];
__device__ float g_TIE  [HHEADS*RR*LL];
__device__ float g_DOTS1[HHEADS*LL*LL];
__device__ float g_DOTS2[HHEADS*LL*LL];
__device__ float g_DOTS3[HHEADS*LL*LL];
__device__ float g_DOTS4[HHEADS*LL*LL];
__device__ float g_PB  [HHEADS*LL*LL];
__device__ float g_ATT [HHEADS*LL*LL];
__device__ float g_WtW [1536*DDIM];
__device__ float g_WtH [LDH*DDIM];
__device__ float g_WtO [DDIM*LDC2];
__device__ float g_WtSq[DDIM*DDIM];
__device__ float g_BH  [LDH];

// ---------------------------------------------------------------------------
__device__ __forceinline__ void mma_tf32(float* d, const uint32_t* a, const uint32_t* b) {
    asm volatile(
        "mma.sync.aligned.m16n8k8.row.col.f32.tf32.tf32.f32 "
        "{%0,%1,%2,%3}, {%4,%5,%6,%7}, {%8,%9}, {%0,%1,%2,%3};"
        : "+f"(d[0]), "+f"(d[1]), "+f"(d[2]), "+f"(d[3])
        : "r"(a[0]), "r"(a[1]), "r"(a[2]), "r"(a[3]), "r"(b[0]), "r"(b[1]));
}
__device__ __forceinline__ uint32_t f2tf32(float v) {
    uint32_t o;
    asm("cvt.rna.tf32.f32 %0, %1;" : "=r"(o) : "f"(v));
    return o;
}
__device__ __forceinline__ float tf32f(float v) {
    return __uint_as_float(f2tf32(v));
}
__device__ __forceinline__ uint32_t smem_u32(const void* p) {
    uint32_t a;
    asm("{ .reg .u64 t; cvta.to.shared.u64 t, %1; cvt.u32.u64 %0, t; }"
        : "=r"(a) : "l"(p));
    return a;
}
__device__ __forceinline__ void cp16(uint32_t dst, const void* src) {
    asm volatile("cp.async.ca.shared.global [%0], [%1], 16;" :: "r"(dst), "l"(src));
}
__device__ __forceinline__ void pipe_wait(bool more) {
    if (more) asm volatile("cp.async.wait_group 1;");
    else      asm volatile("cp.async.wait_group 0;");
}
__device__ __forceinline__ void ldsmA(uint32_t* af, uint32_t base, int strw,
                                      int rw, int ks, int lane) {
    int j = lane & 7, sel = lane >> 3;
    uint32_t addr = base + (uint32_t)(((rw + (sel & 1) * 8 + j) * strw
                                       + ks + (sel >> 1) * 4) << 2);
    asm volatile("ldmatrix.sync.aligned.m8n8.x4.shared.b16 {%0,%1,%2,%3}, [%4];"
        : "=r"(af[0]), "=r"(af[1]), "=r"(af[2]), "=r"(af[3]) : "r"(addr));
}
__device__ __forceinline__ void ldsmB4(uint32_t* bf, uint32_t base, int strw,
                                       int n0, int ks, int lane) {
    int j = lane & 7, g = lane >> 3;
    uint32_t addr = base + (uint32_t)(((n0 + (g >> 1) * 8 + j) * strw
                                       + ks + (g & 1) * 4) << 2);
    asm volatile("ldmatrix.sync.aligned.m8n8.x4.shared.b16 {%0,%1,%2,%3}, [%4];"
        : "=r"(bf[0]), "=r"(bf[1]), "=r"(bf[2]), "=r"(bf[3]) : "r"(addr));
}

// ---------------------------------------------------------------------------
__global__ __launch_bounds__(256) void cvt_k(const float* __restrict__ s,
                                             float* __restrict__ d)
{
    int i = (blockIdx.x * 256 + threadIdx.x) * 4;
    float4 v = *(const float4*)&s[i];
    v.x = tf32f(v.x); v.y = tf32f(v.y); v.z = tf32f(v.z); v.w = tf32f(v.w);
    *(float4*)&d[i] = v;
}

__global__ void biasext_k(const float* __restrict__ bsk, float* __restrict__ be)
{
    int i = blockIdx.x * 256 + threadIdx.x;
    if (i < LDH) be[i] = (i >= 1536) ? bsk[i - 1536] : 0.f;
}

__global__ __launch_bounds__(128) void scaleq_k(
    const float* __restrict__ TIE, const float* __restrict__ QKVH,
    float* __restrict__ QW)
{
    const int i = blockIdx.x;
    const int r = blockIdx.y;
    const int t = threadIdx.x;
    const int h = t >> 4;
    const size_t row = (size_t)r * LL + i;
    float wv = TIE[((size_t)h * RR + r) * LL + i];
    float4 v = *(const float4*)&QKVH[row * LDH + t * 4];
    v.x = tf32f(v.x * wv); v.y = tf32f(v.y * wv);
    v.z = tf32f(v.z * wv); v.w = tf32f(v.w * wv);
    *(float4*)&QW[row * INNERD + t * 4] = v;
}

// ---------------------------------------------------------------------------
__global__ void transpose_k(const float* __restrict__ W, float* __restrict__ Wt,
                            int N, int ldt)
{
    __shared__ float tile[32][33];
    int kb = blockIdx.y * 32, nb = blockIdx.x * 32;
    int tx = threadIdx.x, ty = threadIdx.y;
#pragma unroll
    for (int i = 0; i < 32; i += 8)
        tile[ty + i][tx] = W[(size_t)(kb + ty + i) * N + nb + tx];
    __syncthreads();
#pragma unroll
    for (int i = 0; i < 32; i += 8)
        Wt[(size_t)(nb + ty + i) * ldt + kb + tx] = tf32f(tile[tx][ty + i]);
}

// Fused transpose of two weight matrices (shared output, K=128, ldt=DDIM)
__global__ void transpose2_k(const float* __restrict__ W1, int N1,
                             const float* __restrict__ W2, int N2,
                             float* __restrict__ Wt)
{
    __shared__ float tile[32][33];
    int kb = blockIdx.y * 32, nb = blockIdx.x * 32;
    int tx = threadIdx.x, ty = threadIdx.y;
    const float* W; int N; int nbl;
    if (nb < N1) { W = W1; N = N1; nbl = nb; }
    else         { W = W2; N = N2; nbl = nb - N1; }
#pragma unroll
    for (int i = 0; i < 32; i += 8)
        tile[ty + i][tx] = W[(size_t)(kb + ty + i) * N + nbl + tx];
    __syncthreads();
#pragma unroll
    for (int i = 0; i < 32; i += 8)
        Wt[(size_t)(nb + ty + i) * DDIM + kb + tx] = tf32f(tile[tx][ty + i]);
}

// ---------------------------------------------------------------------------
// tf32 GEMM, 3-stage cp.async pipeline, x4 B-fragment loads.
// ---------------------------------------------------------------------------
#define GEMM_SMEM (6 * 2560 * 4)
__global__ __launch_bounds__(256) void gemm_tc(
    const float* __restrict__ X, int ldx,
    const float* __restrict__ Wt, int ldw,
    const float* __restrict__ b1, const float* __restrict__ b2,
    float* __restrict__ C, int ldc,
    int K, float alpha)
{
    extern __shared__ float smg[];
    const int t    = threadIdx.x;
    const int lane = t & 31;
    const int wid  = t >> 5;
    const int wm   = (wid & 3) * 32;
    const int wn   = (wid >> 2) * 64;
    const int row0 = blockIdx.y * 128;
    const int col0 = blockIdx.x * 128;
    const int lr = t >> 2;
    const int lc = (t & 3) * 4;
    const uint32_t base = smem_u32(smg);

    float acc[2][8][4];
#pragma unroll
    for (int mt = 0; mt < 2; mt++)
#pragma unroll
        for (int nt = 0; nt < 8; nt++)
#pragma unroll
            for (int i = 0; i < 4; i++) acc[mt][nt][i] = 0.f;

    auto issue = [&](int c) {
        int s = c % 3;
        int k0 = c << 4;
        uint32_t aS = base + (uint32_t)(s * 2560) * 4;
        uint32_t bS = base + (uint32_t)((3 + s) * 2560) * 4;
#pragma unroll
        for (int half = 0; half < 2; half++) {
            int r = lr + half * 64;
            cp16(aS + (uint32_t)(r * 20 + lc) * 4,
                 &X[(size_t)(row0 + r) * ldx + k0 + lc]);
            cp16(bS + (uint32_t)(r * 20 + lc) * 4,
                 &Wt[(size_t)(col0 + r) * ldw + k0 + lc]);
        }
        asm volatile("cp.async.commit_group;");
    };

    const int nc = K >> 4;
    issue(0);
    if (nc > 1) issue(1);
    for (int c = 0; c < nc; c++) {
        pipe_wait(c + 1 < nc);
        __syncthreads();
        if (c + 2 < nc) issue(c + 2);
        const int s = c % 3;
        const uint32_t aS = base + (uint32_t)(s * 2560) * 4;
        const uint32_t bS = base + (uint32_t)((3 + s) * 2560) * 4;
#pragma unroll
        for (int ks = 0; ks < 16; ks += 8) {
            uint32_t af[2][4];
            ldsmA(af[0], aS, 20, wm,      ks, lane);
            ldsmA(af[1], aS, 20, wm + 16, ks, lane);
#pragma unroll
            for (int nt = 0; nt < 8; nt += 2) {
                uint32_t bf[4];
                ldsmB4(bf, bS, 20, wn + nt * 8, ks, lane);
                mma_tf32(acc[0][nt],     af[0], bf);
                mma_tf32(acc[1][nt],     af[1], bf);
                mma_tf32(acc[0][nt + 1], af[0], bf + 2);
                mma_tf32(acc[1][nt + 1], af[1], bf + 2);
            }
        }
    }

#pragma unroll
    for (int mt = 0; mt < 2; mt++) {
#pragma unroll
        for (int nt = 0; nt < 8; nt++) {
            int rg = row0 + wm + mt * 16 + (lane >> 2);
            int cg = col0 + wn + nt * 8 + (lane & 3) * 2;
            float bx = 0.f, by = 0.f;
            if (b1) { bx += b1[cg]; by += b1[cg + 1]; }
            if (b2) { bx += b2[cg]; by += b2[cg + 1]; }
#pragma unroll
            for (int half = 0; half < 2; half++) {
                int r = rg + half * 8;
                float2 v = {alpha * (acc[mt][nt][half * 2 + 0] + bx),
                            alpha * (acc[mt][nt][half * 2 + 1] + by)};
                *(float2*)&C[(size_t)r * ldc + cg] = v;
            }
        }
    }
}

// ---------------------------------------------------------------------------
// dots_tc: 4-way K-split (rz in 0..3 over r ranges of 32), 288 blocks.
// ---------------------------------------------------------------------------
#define DOTS_SMEM (6 * 4608 * 4)
__global__ __launch_bounds__(256) void dots_tc(
    const float* __restrict__ QW, const float* __restrict__ QKVH,
    float* __restrict__ D1, float* __restrict__ D2,
    float* __restrict__ D3, float* __restrict__ D4)
{
    extern __shared__ float smd[];
    const int t    = threadIdx.x;
    const int lane = t & 31;
    const int wid  = t >> 5;
    const int wm   = (wid & 3) * 32;
    const int wn   = (wid >> 2) * 64;
    const int i0 = blockIdx.y * 128;
    const int j0 = blockIdx.x * 128;
    const int h  = blockIdx.z & 7;
    const int rz = blockIdx.z >> 3;         // 0..3
    const int r00 = rz * 32;
    const uint32_t base = smem_u32(smd);

    float acc[2][8][4];
#pragma unroll
    for (int mt = 0; mt < 2; mt++)
#pragma unroll
        for (int nt = 0; nt < 8; nt++)
#pragma unroll
            for (int i = 0; i < 4; i++) acc[mt][nt][i] = 0.f;

    const int lr = t >> 1;
    const int lc = (t & 1) * 16;

    auto issue = [&](int c) {
        int s = c % 3;
        int r = r00 + (c >> 1);
        int d0 = (c & 1) * 32;
        uint32_t aS = base + (uint32_t)(s * 4608 + lr * 36 + lc) * 4;
        uint32_t bS = base + (uint32_t)((3 + s) * 4608 + lr * 36 + lc) * 4;
        const float* asrc = &QW[((size_t)r * LL + i0 + lr) * INNERD + h * DHEAD + d0 + lc];
        const float* bsrc = &QKVH[((size_t)r * LL + j0 + lr) * LDH + 512 + h * DHEAD + d0 + lc];
#pragma unroll
        for (int u = 0; u < 16; u += 4) {
            cp16(aS + u * 4, asrc + u);
            cp16(bS + u * 4, bsrc + u);
        }
        asm volatile("cp.async.commit_group;");
    };

    const int nc = 64;                      // 32 r x 2 segs
    issue(0); issue(1);
    for (int c = 0; c < nc; c++) {
        pipe_wait(c + 1 < nc);
        __syncthreads();
        if (c + 2 < nc) issue(c + 2);
        const int s = c % 3;
        const uint32_t aS = base + (uint32_t)(s * 4608) * 4;
        const uint32_t bS = base + (uint32_t)((3 + s) * 4608) * 4;
#pragma unroll
        for (int ks = 0; ks < 32; ks += 8) {
            uint32_t af[2][4];
            ldsmA(af[0], aS, 36, wm,      ks, lane);
            ldsmA(af[1], aS, 36, wm + 16, ks, lane);
#pragma unroll
            for (int nt = 0; nt < 8; nt += 2) {
                uint32_t bf[4];
                ldsmB4(bf, bS, 36, wn + nt * 8, ks, lane);
                mma_tf32(acc[0][nt],     af[0], bf);
                mma_tf32(acc[1][nt],     af[1], bf);
                mma_tf32(acc[0][nt + 1], af[0], bf + 2);
                mma_tf32(acc[1][nt + 1], af[1], bf + 2);
            }
        }
    }

    float* OUT = (rz == 0 ? D1 : rz == 1 ? D2 : rz == 2 ? D3 : D4)
                 + (size_t)h * LL * LL;
#pragma unroll
    for (int mt = 0; mt < 2; mt++) {
#pragma unroll
        for (int nt = 0; nt < 8; nt++) {
            int rg = i0 + wm + mt * 16 + (lane >> 2);
            int cg = j0 + wn + nt * 8 + (lane & 3) * 2;
#pragma unroll
            for (int half = 0; half < 2; half++) {
                int rw = rg + half * 8;
                float2 v = {0.125f * acc[mt][nt][half * 2 + 0],
                            0.125f * acc[mt][nt][half * 2 + 1]};
                *(float2*)&OUT[(size_t)rw * LL + cg] = v;
            }
        }
    }
}

// ---------------------------------------------------------------------------
// Tensor-core column attention (unchanged structure).
// ---------------------------------------------------------------------------
__global__ __launch_bounds__(256, 2) void col_attn_tc(
    const float* __restrict__ QKV, float* __restrict__ CWH)
{
    extern __shared__ float sm[];
    float* Qs = sm;
    float* Ks = sm + 128 * 68;
    float* P  = sm;
    float* Vt = sm + 2 * 128 * 68;

    const int l = blockIdx.x >> 3;
    const int h = blockIdx.x & 7;
    const int t = threadIdx.x;
    const int lane = t & 31;
    const int wid  = t >> 5;
    const int wm   = wid * 16;
    const int fr   = lane >> 2;
    const int q2   = (lane & 3) * 2;
    const size_t RS = (size_t)LL * LDW;
    const uint32_t qsu = smem_u32(Qs);
    const uint32_t ksu = smem_u32(Ks);
    const uint32_t psu = smem_u32(P);
    const uint32_t vsu = smem_u32(Vt);

    const float* qb = QKV + (size_t)l * LDW + h * DHEAD;
    const float* kb = qb + 512;
    const float* vb = qb + 1024;

    for (int idx = t; idx < 2048; idx += 256) {
        int row = idx >> 4, c4 = (idx & 15) * 4;
        float4 a = *(const float4*)(qb + row * RS + c4);
        float4 b = *(const float4*)(kb + row * RS + c4);
        *(float4*)&Qs[row * 68 + c4] = a;
        *(float4*)&Ks[row * 68 + c4] = b;
    }
    __syncthreads();

    float acc[16][4];
#pragma unroll
    for (int nt = 0; nt < 16; nt++)
#pragma unroll
        for (int i = 0; i < 4; i++) acc[nt][i] = 0.f;

#pragma unroll
    for (int ks = 0; ks < 64; ks += 8) {
        uint32_t af[4];
        ldsmA(af, qsu, 68, wm, ks, lane);
#pragma unroll
        for (int nt = 0; nt < 16; nt += 2) {
            uint32_t bf[4];
            ldsmB4(bf, ksu, 68, nt * 8, ks, lane);
            mma_tf32(acc[nt],     af, bf);
            mma_tf32(acc[nt + 1], af, bf + 2);
        }
    }

    float mx0 = -1e30f, mx1 = -1e30f;
#pragma unroll
    for (int nt = 0; nt < 16; nt++) {
        mx0 = fmaxf(mx0, fmaxf(acc[nt][0], acc[nt][1]));
        mx1 = fmaxf(mx1, fmaxf(acc[nt][2], acc[nt][3]));
    }
    mx0 = fmaxf(mx0, __shfl_xor_sync(0xffffffffu, mx0, 1));
    mx0 = fmaxf(mx0, __shfl_xor_sync(0xffffffffu, mx0, 2));
    mx1 = fmaxf(mx1, __shfl_xor_sync(0xffffffffu, mx1, 1));
    mx1 = fmaxf(mx1, __shfl_xor_sync(0xffffffffu, mx1, 2));
    float s0 = 0.f, s1 = 0.f;
#pragma unroll
    for (int nt = 0; nt < 16; nt++) {
        acc[nt][0] = __expf(0.125f * (acc[nt][0] - mx0)); s0 += acc[nt][0];
        acc[nt][1] = __expf(0.125f * (acc[nt][1] - mx0)); s0 += acc[nt][1];
        acc[nt][2] = __expf(0.125f * (acc[nt][2] - mx1)); s1 += acc[nt][2];
        acc[nt][3] = __expf(0.125f * (acc[nt][3] - mx1)); s1 += acc[nt][3];
    }
    s0 += __shfl_xor_sync(0xffffffffu, s0, 1);
    s0 += __shfl_xor_sync(0xffffffffu, s0, 2);
    s1 += __shfl_xor_sync(0xffffffffu, s1, 1);
    s1 += __shfl_xor_sync(0xffffffffu, s1, 2);

    __syncthreads();

#pragma unroll
    for (int nt = 0; nt < 16; nt++) {
        float2 p0 = {tf32f(acc[nt][0]), tf32f(acc[nt][1])};
        float2 p1 = {tf32f(acc[nt][2]), tf32f(acc[nt][3])};
        *(float2*)&P[(wm + fr) * 132 + nt * 8 + q2]     = p0;
        *(float2*)&P[(wm + fr + 8) * 132 + nt * 8 + q2] = p1;
    }
    for (int idx = t; idx < 2048; idx += 256) {
        int j = idx >> 4, c4 = (idx & 15) * 4;
        float4 v = *(const float4*)(vb + j * RS + c4);
        Vt[(c4 + 0) * 132 + j] = v.x;
        Vt[(c4 + 1) * 132 + j] = v.y;
        Vt[(c4 + 2) * 132 + j] = v.z;
        Vt[(c4 + 3) * 132 + j] = v.w;
    }
    __syncthreads();

    float o[8][4];
#pragma unroll
    for (int nt = 0; nt < 8; nt++)
#pragma unroll
        for (int i = 0; i < 4; i++) o[nt][i] = 0.f;

#pragma unroll
    for (int ks = 0; ks < 128; ks += 8) {
        uint32_t af[4];
        ldsmA(af, psu, 132, wm, ks, lane);
#pragma unroll
        for (int nt = 0; nt < 8; nt += 2) {
            uint32_t bf[4];
            ldsmB4(bf, vsu, 132, nt * 8, ks, lane);
            mma_tf32(o[nt],     af, bf);
            mma_tf32(o[nt + 1], af, bf + 2);
        }
    }

    const float inv0 = 1.f / s0, inv1 = 1.f / s1;
    float* ow = CWH + (size_t)l * LDC2 + h * DHEAD;
    const size_t OS = (size_t)LL * LDC2;
#pragma unroll
    for (int nt = 0; nt < 8; nt++) {
        int cg = nt * 8 + q2;
        float2 v0 = {tf32f(o[nt][0] * inv0), tf32f(o[nt][1] * inv0)};
        float2 v1 = {tf32f(o[nt][2] * inv1), tf32f(o[nt][3] * inv1)};
        *(float2*)(ow + (size_t)(wm + fr) * OS + cg)     = v0;
        *(float2*)(ow + (size_t)(wm + fr + 8) * OS + cg) = v1;
    }
}

// ---------------------------------------------------------------------------
// oh_tc (unchanged)
// ---------------------------------------------------------------------------
__global__ __launch_bounds__(256) void oh_tc(
    const float* __restrict__ ATT, const float* __restrict__ QKV,
    float* __restrict__ CWH)
{
    __shared__ float As[128 * 20];
    __shared__ float Bs[64 * 20];

    const int t    = threadIdx.x;
    const int lane = t & 31;
    const int wid  = t >> 5;
    const int wm   = (wid & 3) * 32;
    const int wn   = (wid >> 2) * 32;
    const int i0 = blockIdx.x * 128;
    const int r  = blockIdx.y >> 3;
    const int h  = blockIdx.y & 7;
    const uint32_t asu = smem_u32(As);
    const uint32_t bsu = smem_u32(Bs);

    float acc[2][4][4];
#pragma unroll
    for (int mt = 0; mt < 2; mt++)
#pragma unroll
        for (int nt = 0; nt < 4; nt++)
#pragma unroll
            for (int i = 0; i < 4; i++) acc[mt][nt][i] = 0.f;

    for (int k0 = 0; k0 < LL; k0 += 16) {
#pragma unroll
        for (int i = 0; i < 2; i++) {
            int idx = t + 256 * i;
            int row = idx >> 2, c4 = (idx & 3) * 4;
            float4 va = *(const float4*)&ATT[((size_t)h * LL + i0 + row) * LL + k0 + c4];
            uint4 ua;
            ua.x = f2tf32(va.x); ua.y = f2tf32(va.y);
            ua.z = f2tf32(va.z); ua.w = f2tf32(va.w);
            *(uint4*)&As[row * 20 + c4] = ua;
        }
        {
            int kr = t >> 4;
            int dc = (t & 15) * 4;
            float4 vb = *(const float4*)&QKV[((size_t)(r * LL + k0 + kr)) * LDH + 1024 + h * DHEAD + dc];
            Bs[(dc + 0) * 20 + kr] = vb.x;
            Bs[(dc + 1) * 20 + kr] = vb.y;
            Bs[(dc + 2) * 20 + kr] = vb.z;
            Bs[(dc + 3) * 20 + kr] = vb.w;
        }
        __syncthreads();
#pragma unroll
        for (int ks = 0; ks < 16; ks += 8) {
            uint32_t af[2][4];
            ldsmA(af[0], asu, 20, wm,      ks, lane);
            ldsmA(af[1], asu, 20, wm + 16, ks, lane);
#pragma unroll
            for (int nt = 0; nt < 4; nt += 2) {
                uint32_t bf[4];
                ldsmB4(bf, bsu, 20, wn + nt * 8, ks, lane);
                mma_tf32(acc[0][nt],     af[0], bf);
                mma_tf32(acc[1][nt],     af[1], bf);
                mma_tf32(acc[0][nt + 1], af[0], bf + 2);
                mma_tf32(acc[1][nt + 1], af[1], bf + 2);
            }
        }
        __syncthreads();
    }

#pragma unroll
    for (int mt = 0; mt < 2; mt++) {
#pragma unroll
        for (int nt = 0; nt < 4; nt++) {
            int rloc = i0 + wm + mt * 16 + (lane >> 2);
            int cg   = wn + nt * 8 + (lane & 3) * 2;
#pragma unroll
            for (int half = 0; half < 2; half++) {
                int rw = rloc + half * 8;
                float2 v = {tf32f(acc[mt][nt][half * 2 + 0]),
                            tf32f(acc[mt][nt][half * 2 + 1])};
                *(float2*)&CWH[((size_t)(r * LL + rw)) * LDC2 + 512 + h * DHEAD + cg] = v;
            }
        }
    }
}

// ---------------------------------------------------------------------------
__global__ __launch_bounds__(128) void tie_k(
    const float* __restrict__ QS, const float* __restrict__ QKV,
    float* __restrict__ TIE)
{
    const int l = blockIdx.x >> 3;
    const int h = blockIdx.x & 7;
    const int r = threadIdx.x;
    const float* q = &QS[l * DDIM + h * DHW];
    const float* k = &QKV[((size_t)r * LL + l) * LDH + 1536 + h * DHW];
    float s = 0.f;
#pragma unroll
    for (int d = 0; d < DHW; d++) s += q[d] * k[d];
    s *= 0.25f;

    __shared__ float red[128];
    red[r] = s; __syncthreads();
    for (int o = 64; o; o >>= 1) { if (r < o) red[r] = fmaxf(red[r], red[r + o]); __syncthreads(); }
    float m = red[0]; __syncthreads();
    float e = __expf(s - m);
    red[r] = e; __syncthreads();
    for (int o = 64; o; o >>= 1) { if (r < o) red[r] += red[r + o]; __syncthreads(); }
    TIE[((size_t)h * RR + r) * LL + l] = e / red[0];
}

// ---------------------------------------------------------------------------
__global__ __launch_bounds__(128) void pb_k(
    const float* __restrict__ pair, const float* __restrict__ gam,
    const float* __restrict__ bet, const float* __restrict__ Wp,
    float* __restrict__ PB)
{
    const int w    = threadIdx.x >> 5;
    const int lane = threadIdx.x & 31;
    const int pid  = blockIdx.x * 4 + w;
    float4 x4 = *(const float4*)&pair[(size_t)pid * DPAIR + lane * 4];
    float x[4] = {x4.x, x4.y, x4.z, x4.w};
    float s1 = x[0] + x[1] + x[2] + x[3];
    float s2 = x[0]*x[0] + x[1]*x[1] + x[2]*x[2] + x[3]*x[3];
#pragma unroll
    for (int o = 16; o; o >>= 1) {
        s1 += __shfl_xor_sync(0xffffffffu, s1, o);
        s2 += __shfl_xor_sync(0xffffffffu, s2, o);
    }
    float mu  = s1 * (1.f / DPAIR);
    float var = s2 * (1.f / DPAIR) - mu * mu;
    float inv = rsqrtf(var + 1e-5f);

    float acc[8];
#pragma unroll
    for (int hh = 0; hh < 8; hh++) acc[hh] = 0.f;
#pragma unroll
    for (int u = 0; u < 4; u++) {
        int c = lane * 4 + u;
        float nx = (x[u] - mu) * inv * gam[c] + bet[c];
#pragma unroll
        for (int hh = 0; hh < 8; hh++) acc[hh] += nx * Wp[c * 8 + hh];
    }
#pragma unroll
    for (int o = 16; o; o >>= 1)
#pragma unroll
        for (int hh = 0; hh < 8; hh++) acc[hh] += __shfl_xor_sync(0xffffffffu, acc[hh], o);
    if (lane == 0) {
#pragma unroll
        for (int hh = 0; hh < 8; hh++) PB[(size_t)hh * LL * LL + pid] = acc[hh];
    }
}

// ---------------------------------------------------------------------------
__global__ __launch_bounds__(128) void softh_k(
    const float* __restrict__ D1, const float* __restrict__ D2,
    const float* __restrict__ D3, const float* __restrict__ D4,
    const float* __restrict__ PB, float* __restrict__ ATT)
{
    const int i = blockIdx.x;
    const int h = blockIdx.y;
    const int t = threadIdx.x;
    const size_t base = ((size_t)h * LL + i) * LL;
    const float* dp1 = D1 + base;
    const float* dp2 = D2 + base;
    const float* dp3 = D3 + base;
    const float* dp4 = D4 + base;
    const float* pb  = PB + base;
    float x[3];
#pragma unroll
    for (int u = 0; u < 3; u++) {
        int j = t + u * 128;
        x[u] = (dp1[j] + dp2[j]) + (dp3[j] + dp4[j]) + pb[j];
    }
    __shared__ float red[128];
    float lm = fmaxf(fmaxf(x[0], x[1]), x[2]);
    red[t] = lm; __syncthreads();
    for (int o = 64; o; o >>= 1) { if (t < o) red[t] = fmaxf(red[t], red[t + o]); __syncthreads(); }
    float mx = red[0]; __syncthreads();
    float e[3], ls = 0.f;
#pragma unroll
    for (int u = 0; u < 3; u++) { e[u] = __expf(x[u] - mx); ls += e[u]; }
    red[t] = ls; __syncthreads();
    for (int o = 64; o; o >>= 1) { if (t < o) red[t] += red[t + o]; __syncthreads(); }
    float inv = 1.f / red[0];
    float* ap = ATT + base;
#pragma unroll
    for (int u = 0; u < 3; u++) ap[t + u * 128] = e[u] * inv;
}

// ---------------------------------------------------------------------------
static float* sym(const void* s) {
    void* p = nullptr;
    cudaGetSymbolAddress(&p, s);
    return (float*)p;
}

extern "C" void kernel_launch(void* const* d_in, const int* in_sizes, int n_in,
                              void* d_out, int out_size)
{
    const float* m     = (const float*)d_in[0];
    const float* pair  = (const float*)d_in[1];
    const float* Wq_w  = (const float*)d_in[2];
    const float* Wkv_w = (const float*)d_in[3];
    const float* Wo_w  = (const float*)d_in[4];
    const float* bo_w  = (const float*)d_in[5];
    const float* Wq_h  = (const float*)d_in[6];
    const float* Wkv_h = (const float*)d_in[7];
    const float* Wo_h  = (const float*)d_in[8];
    const float* bo_h  = (const float*)d_in[9];
    const float* ln_g  = (const float*)d_in[10];
    const float* ln_b  = (const float*)d_in[11];
    const float* Wpair = (const float*)d_in[12];
    const float* Wsq   = (const float*)d_in[13];
    const float* bsq   = (const float*)d_in[14];
    const float* Wsk   = (const float*)d_in[15];
    const float* bsk   = (const float*)d_in[16];
    float* out = (float*)d_out;

    float* Mt    = sym(g_Mt);
    float* QKVW  = sym(g_QKVW);
    float* QKVH  = sym(g_QKVH);
    float* QW    = sym(g_QW);
    float* CWH   = sym(g_CWH);
    float* QS    = sym(g_QS);
    float* TIE   = sym(g_TIE);
    float* DOTS1 = sym(g_DOTS1);
    float* DOTS2 = sym(g_DOTS2);
    float* DOTS3 = sym(g_DOTS3);
    float* DOTS4 = sym(g_DOTS4);
    float* PB    = sym(g_PB);
    float* ATT   = sym(g_ATT);
    float* WtW   = sym(g_WtW);
    float* WtH   = sym(g_WtH);
    float* WtO   = sym(g_WtO);
    float* WtSq  = sym(g_WtSq);
    float* BH    = sym(g_BH);

    const int CA_SMEM = (2 * 128 * 68 + 64 * 132) * 4;
    cudaFuncSetAttribute(col_attn_tc, cudaFuncAttributeMaxDynamicSharedMemorySize, CA_SMEM);
    cudaFuncSetAttribute(gemm_tc, cudaFuncAttributeMaxDynamicSharedMemorySize, GEMM_SMEM);
    cudaFuncSetAttribute(dots_tc, cudaFuncAttributeMaxDynamicSharedMemorySize, DOTS_SMEM);

    static cudaStream_t sB = nullptr, sC = nullptr;
    static cudaEvent_t evMt, evPB, evB, evC;
    if (sB == nullptr) {
        cudaStreamCreateWithFlags(&sB, cudaStreamNonBlocking);
        cudaStreamCreateWithFlags(&sC, cudaStreamNonBlocking);
        cudaEventCreateWithFlags(&evMt, cudaEventDisableTiming);
        cudaEventCreateWithFlags(&evPB, cudaEventDisableTiming);
        cudaEventCreateWithFlags(&evB,  cudaEventDisableTiming);
        cudaEventCreateWithFlags(&evC,  cudaEventDisableTiming);
    }

    const dim3 tb(32, 8);

    // ---- stream 0: width path (#4 = ncu capture slot = col_attn_tc) ----
    cvt_k<<<ML * DDIM / 1024, 256>>>(m, Mt);                                   // #1
    cudaEventRecord(evMt, 0);
    transpose2_k<<<dim3(48, 4), tb>>>(Wq_w, INNERD, Wkv_w, 2 * INNERD, WtW);   // #2
    gemm_tc<<<dim3(12, 384), 256, GEMM_SMEM>>>(Mt, DDIM, WtW, DDIM, nullptr, nullptr,
                                               QKVW, LDW, DDIM, 1.f);          // #3
    col_attn_tc<<<LL * HHEADS, 256, CA_SMEM>>>(QKVW, CWH);                     // #4 (ncu)

    // ---- stream B: height path ----
    cudaStreamWaitEvent(sB, evMt, 0);
    transpose2_k<<<dim3(48, 4), tb, 0, sB>>>(Wq_h, INNERD, Wkv_h, 2 * INNERD, WtH);
    transpose_k<<<dim3(4, 4),  tb, 0, sB>>>(Wsk,   WtH + 1536 * DDIM, DDIM, DDIM);
    transpose_k<<<dim3(4, 4),  tb, 0, sB>>>(Wsq,   WtSq,              DDIM, DDIM);
    biasext_k<<<(LDH + 255) / 256, 256, 0, sB>>>(bsk, BH);
    gemm_tc<<<dim3(13, 384), 256, GEMM_SMEM, sB>>>(Mt, DDIM, WtH, DDIM, BH, nullptr,
                                                   QKVH, LDH, DDIM, 1.f);
    gemm_tc<<<dim3(1, 3), 256, GEMM_SMEM, sB>>>(Mt, DDIM, WtSq, DDIM, bsq, nullptr,
                                                QS, DDIM, DDIM, 1.f);
    tie_k<<<LL * HHEADS, 128, 0, sB>>>(QS, QKVH, TIE);
    scaleq_k<<<dim3(LL, RR), 128, 0, sB>>>(TIE, QKVH, QW);
    dots_tc<<<dim3(3, 3, 32), 256, DOTS_SMEM, sB>>>(QW, QKVH,
                                                    DOTS1, DOTS2, DOTS3, DOTS4);

    // ---- stream C: pair bias + output-weight prep ----
    cudaStreamWaitEvent(sC, evMt, 0);
    pb_k<<<LL * LL / 4, 128, 0, sC>>>(pair, ln_g, ln_b, Wpair, PB);
    cudaEventRecord(evPB, sC);
    transpose_k<<<dim3(4, 16), tb, 0, sC>>>(Wo_w, WtO,       DDIM, LDC2);
    transpose_k<<<dim3(4, 16), tb, 0, sC>>>(Wo_h, WtO + 512, DDIM, LDC2);
    cudaEventRecord(evC, sC);

    // ---- stream B tail ----
    cudaStreamWaitEvent(sB, evPB, 0);
    softh_k<<<dim3(LL, HHEADS), 128, 0, sB>>>(DOTS1, DOTS2, DOTS3, DOTS4, PB, ATT);
    oh_tc<<<dim3(3, RR * HHEADS), 256, 0, sB>>>(ATT, QKVH, CWH);
    cudaEventRecord(evB, sB);

    // ---- join: fused output GEMM ----
    cudaStreamWaitEvent(0, evB, 0);
    cudaStreamWaitEvent(0, evC, 0);
    gemm_tc<<<dim3(1, 384), 256, GEMM_SMEM>>>(CWH, LDC2, WtO, LDC2, bo_w, bo_h,
                                              out, DDIM, LDC2, 0.5f);
}

// round 17
// speedup vs baseline: 1.0655x; 1.0197x over previous
#include <cuda_runtime.h>
#include <cuda_fp16.h>
#include <cstdint>

#define RR     128
#define LL     384
#define DDIM   128
#define HHEADS 8
#define DHEAD  64
#define DPAIR  128
#define INNERD 512
#define ML     (RR*LL)
#define DHW    16
#define LDW    1536
#define LDH    1664
#define LDC2   1024

// ---------------- scratch ----------
__device__ float  g_Mt  [ML*DDIM];
__device__ __half g_QKVW[ML*LDW];          // fp16: width Q|K|V
__device__ float  g_QKVH[ML*LDH];
__device__ float  g_QW  [ML*INNERD];
__device__ float  g_CWH [ML*LDC2];
__device__ float  g_QS  [LL*DDIM];
__device__ float  g_TIE  [HHEADS*RR*LL];
__device__ float  g_DOTS1[HHEADS*LL*LL];
__device__ float  g_DOTS2[HHEADS*LL*LL];
__device__ float  g_DOTS3[HHEADS*LL*LL];
__device__ float  g_DOTS4[HHEADS*LL*LL];
__device__ float  g_PB  [HHEADS*LL*LL];
__device__ float  g_ATT [HHEADS*LL*LL];
__device__ float  g_WtW [1536*DDIM];
__device__ float  g_WtH [LDH*DDIM];
__device__ float  g_WtO [DDIM*LDC2];
__device__ float  g_WtSq[DDIM*DDIM];
__device__ float  g_BH  [LDH];

// ---------------------------------------------------------------------------
__device__ __forceinline__ void mma_tf32(float* d, const uint32_t* a, const uint32_t* b) {
    asm volatile(
        "mma.sync.aligned.m16n8k8.row.col.f32.tf32.tf32.f32 "
        "{%0,%1,%2,%3}, {%4,%5,%6,%7}, {%8,%9}, {%0,%1,%2,%3};"
        : "+f"(d[0]), "+f"(d[1]), "+f"(d[2]), "+f"(d[3])
        : "r"(a[0]), "r"(a[1]), "r"(a[2]), "r"(a[3]), "r"(b[0]), "r"(b[1]));
}
__device__ __forceinline__ uint32_t f2tf32(float v) {
    uint32_t o;
    asm("cvt.rna.tf32.f32 %0, %1;" : "=r"(o) : "f"(v));
    return o;
}
__device__ __forceinline__ float tf32f(float v) {
    return __uint_as_float(f2tf32(v));
}
__device__ __forceinline__ uint32_t smem_u32(const void* p) {
    uint32_t a;
    asm("{ .reg .u64 t; cvta.to.shared.u64 t, %1; cvt.u32.u64 %0, t; }"
        : "=r"(a) : "l"(p));
    return a;
}
__device__ __forceinline__ void cp16(uint32_t dst, const void* src) {
    asm volatile("cp.async.ca.shared.global [%0], [%1], 16;" :: "r"(dst), "l"(src));
}
__device__ __forceinline__ void pipe_wait(bool more) {
    if (more) asm volatile("cp.async.wait_group 1;");
    else      asm volatile("cp.async.wait_group 0;");
}
__device__ __forceinline__ void ldsmA(uint32_t* af, uint32_t base, int strw,
                                      int rw, int ks, int lane) {
    int j = lane & 7, sel = lane >> 3;
    uint32_t addr = base + (uint32_t)(((rw + (sel & 1) * 8 + j) * strw
                                       + ks + (sel >> 1) * 4) << 2);
    asm volatile("ldmatrix.sync.aligned.m8n8.x4.shared.b16 {%0,%1,%2,%3}, [%4];"
        : "=r"(af[0]), "=r"(af[1]), "=r"(af[2]), "=r"(af[3]) : "r"(addr));
}
__device__ __forceinline__ void ldsmB4(uint32_t* bf, uint32_t base, int strw,
                                       int n0, int ks, int lane) {
    int j = lane & 7, g = lane >> 3;
    uint32_t addr = base + (uint32_t)(((n0 + (g >> 1) * 8 + j) * strw
                                       + ks + (g & 1) * 4) << 2);
    asm volatile("ldmatrix.sync.aligned.m8n8.x4.shared.b16 {%0,%1,%2,%3}, [%4];"
        : "=r"(bf[0]), "=r"(bf[1]), "=r"(bf[2]), "=r"(bf[3]) : "r"(addr));
}

// ---------------------------------------------------------------------------
__global__ __launch_bounds__(256) void cvt_k(const float* __restrict__ s,
                                             float* __restrict__ d)
{
    int i = (blockIdx.x * 256 + threadIdx.x) * 4;
    float4 v = *(const float4*)&s[i];
    v.x = tf32f(v.x); v.y = tf32f(v.y); v.z = tf32f(v.z); v.w = tf32f(v.w);
    *(float4*)&d[i] = v;
}

__global__ void biasext_k(const float* __restrict__ bsk, float* __restrict__ be)
{
    int i = blockIdx.x * 256 + threadIdx.x;
    if (i < LDH) be[i] = (i >= 1536) ? bsk[i - 1536] : 0.f;
}

__global__ __launch_bounds__(128) void scaleq_k(
    const float* __restrict__ TIE, const float* __restrict__ QKVH,
    float* __restrict__ QW)
{
    const int i = blockIdx.x;
    const int r = blockIdx.y;
    const int t = threadIdx.x;
    const int h = t >> 4;
    const size_t row = (size_t)r * LL + i;
    float wv = TIE[((size_t)h * RR + r) * LL + i];
    float4 v = *(const float4*)&QKVH[row * LDH + t * 4];
    v.x = tf32f(v.x * wv); v.y = tf32f(v.y * wv);
    v.z = tf32f(v.z * wv); v.w = tf32f(v.w * wv);
    *(float4*)&QW[row * INNERD + t * 4] = v;
}

// ---------------------------------------------------------------------------
__global__ void transpose_k(const float* __restrict__ W, float* __restrict__ Wt,
                            int N, int ldt)
{
    __shared__ float tile[32][33];
    int kb = blockIdx.y * 32, nb = blockIdx.x * 32;
    int tx = threadIdx.x, ty = threadIdx.y;
#pragma unroll
    for (int i = 0; i < 32; i += 8)
        tile[ty + i][tx] = W[(size_t)(kb + ty + i) * N + nb + tx];
    __syncthreads();
#pragma unroll
    for (int i = 0; i < 32; i += 8)
        Wt[(size_t)(nb + ty + i) * ldt + kb + tx] = tf32f(tile[tx][ty + i]);
}

__global__ void transpose2_k(const float* __restrict__ W1, int N1,
                             const float* __restrict__ W2, int N2,
                             float* __restrict__ Wt)
{
    __shared__ float tile[32][33];
    int kb = blockIdx.y * 32, nb = blockIdx.x * 32;
    int tx = threadIdx.x, ty = threadIdx.y;
    const float* W; int N; int nbl;
    if (nb < N1) { W = W1; N = N1; nbl = nb; }
    else         { W = W2; N = N2; nbl = nb - N1; }
#pragma unroll
    for (int i = 0; i < 32; i += 8)
        tile[ty + i][tx] = W[(size_t)(kb + ty + i) * N + nbl + tx];
    __syncthreads();
#pragma unroll
    for (int i = 0; i < 32; i += 8)
        Wt[(size_t)(nb + ty + i) * DDIM + kb + tx] = tf32f(tile[tx][ty + i]);
}

// ---------------------------------------------------------------------------
// tf32 GEMM, 3-stage cp.async pipeline. Optional fp16 output (Ch != nullptr).
// ---------------------------------------------------------------------------
#define GEMM_SMEM (6 * 2560 * 4)
__global__ __launch_bounds__(256) void gemm_tc(
    const float* __restrict__ X, int ldx,
    const float* __restrict__ Wt, int ldw,
    const float* __restrict__ b1, const float* __restrict__ b2,
    float* __restrict__ C, __half* __restrict__ Ch, int ldc,
    int K, float alpha)
{
    extern __shared__ float smg[];
    const int t    = threadIdx.x;
    const int lane = t & 31;
    const int wid  = t >> 5;
    const int wm   = (wid & 3) * 32;
    const int wn   = (wid >> 2) * 64;
    const int row0 = blockIdx.y * 128;
    const int col0 = blockIdx.x * 128;
    const int lr = t >> 2;
    const int lc = (t & 3) * 4;
    const uint32_t base = smem_u32(smg);

    float acc[2][8][4];
#pragma unroll
    for (int mt = 0; mt < 2; mt++)
#pragma unroll
        for (int nt = 0; nt < 8; nt++)
#pragma unroll
            for (int i = 0; i < 4; i++) acc[mt][nt][i] = 0.f;

    auto issue = [&](int c) {
        int s = c % 3;
        int k0 = c << 4;
        uint32_t aS = base + (uint32_t)(s * 2560) * 4;
        uint32_t bS = base + (uint32_t)((3 + s) * 2560) * 4;
#pragma unroll
        for (int half = 0; half < 2; half++) {
            int r = lr + half * 64;
            cp16(aS + (uint32_t)(r * 20 + lc) * 4,
                 &X[(size_t)(row0 + r) * ldx + k0 + lc]);
            cp16(bS + (uint32_t)(r * 20 + lc) * 4,
                 &Wt[(size_t)(col0 + r) * ldw + k0 + lc]);
        }
        asm volatile("cp.async.commit_group;");
    };

    const int nc = K >> 4;
    issue(0);
    if (nc > 1) issue(1);
    for (int c = 0; c < nc; c++) {
        pipe_wait(c + 1 < nc);
        __syncthreads();
        if (c + 2 < nc) issue(c + 2);
        const int s = c % 3;
        const uint32_t aS = base + (uint32_t)(s * 2560) * 4;
        const uint32_t bS = base + (uint32_t)((3 + s) * 2560) * 4;
#pragma unroll
        for (int ks = 0; ks < 16; ks += 8) {
            uint32_t af[2][4];
            ldsmA(af[0], aS, 20, wm,      ks, lane);
            ldsmA(af[1], aS, 20, wm + 16, ks, lane);
#pragma unroll
            for (int nt = 0; nt < 8; nt += 2) {
                uint32_t bf[4];
                ldsmB4(bf, bS, 20, wn + nt * 8, ks, lane);
                mma_tf32(acc[0][nt],     af[0], bf);
                mma_tf32(acc[1][nt],     af[1], bf);
                mma_tf32(acc[0][nt + 1], af[0], bf + 2);
                mma_tf32(acc[1][nt + 1], af[1], bf + 2);
            }
        }
    }

#pragma unroll
    for (int mt = 0; mt < 2; mt++) {
#pragma unroll
        for (int nt = 0; nt < 8; nt++) {
            int rg = row0 + wm + mt * 16 + (lane >> 2);
            int cg = col0 + wn + nt * 8 + (lane & 3) * 2;
            float bx = 0.f, by = 0.f;
            if (b1) { bx += b1[cg]; by += b1[cg + 1]; }
            if (b2) { bx += b2[cg]; by += b2[cg + 1]; }
#pragma unroll
            for (int half = 0; half < 2; half++) {
                int r = rg + half * 8;
                float vx = alpha * (acc[mt][nt][half * 2 + 0] + bx);
                float vy = alpha * (acc[mt][nt][half * 2 + 1] + by);
                if (Ch) {
                    *(__half2*)&Ch[(size_t)r * ldc + cg] = __floats2half2_rn(vx, vy);
                } else {
                    float2 v = {vx, vy};
                    *(float2*)&C[(size_t)r * ldc + cg] = v;
                }
            }
        }
    }
}

// ---------------------------------------------------------------------------
// dots_tc: 4-way K-split (unchanged from round 16)
// ---------------------------------------------------------------------------
#define DOTS_SMEM (6 * 4608 * 4)
__global__ __launch_bounds__(256) void dots_tc(
    const float* __restrict__ QW, const float* __restrict__ QKVH,
    float* __restrict__ D1, float* __restrict__ D2,
    float* __restrict__ D3, float* __restrict__ D4)
{
    extern __shared__ float smd[];
    const int t    = threadIdx.x;
    const int lane = t & 31;
    const int wid  = t >> 5;
    const int wm   = (wid & 3) * 32;
    const int wn   = (wid >> 2) * 64;
    const int i0 = blockIdx.y * 128;
    const int j0 = blockIdx.x * 128;
    const int h  = blockIdx.z & 7;
    const int rz = blockIdx.z >> 3;
    const int r00 = rz * 32;
    const uint32_t base = smem_u32(smd);

    float acc[2][8][4];
#pragma unroll
    for (int mt = 0; mt < 2; mt++)
#pragma unroll
        for (int nt = 0; nt < 8; nt++)
#pragma unroll
            for (int i = 0; i < 4; i++) acc[mt][nt][i] = 0.f;

    const int lr = t >> 1;
    const int lc = (t & 1) * 16;

    auto issue = [&](int c) {
        int s = c % 3;
        int r = r00 + (c >> 1);
        int d0 = (c & 1) * 32;
        uint32_t aS = base + (uint32_t)(s * 4608 + lr * 36 + lc) * 4;
        uint32_t bS = base + (uint32_t)((3 + s) * 4608 + lr * 36 + lc) * 4;
        const float* asrc = &QW[((size_t)r * LL + i0 + lr) * INNERD + h * DHEAD + d0 + lc];
        const float* bsrc = &QKVH[((size_t)r * LL + j0 + lr) * LDH + 512 + h * DHEAD + d0 + lc];
#pragma unroll
        for (int u = 0; u < 16; u += 4) {
            cp16(aS + u * 4, asrc + u);
            cp16(bS + u * 4, bsrc + u);
        }
        asm volatile("cp.async.commit_group;");
    };

    const int nc = 64;
    issue(0); issue(1);
    for (int c = 0; c < nc; c++) {
        pipe_wait(c + 1 < nc);
        __syncthreads();
        if (c + 2 < nc) issue(c + 2);
        const int s = c % 3;
        const uint32_t aS = base + (uint32_t)(s * 4608) * 4;
        const uint32_t bS = base + (uint32_t)((3 + s) * 4608) * 4;
#pragma unroll
        for (int ks = 0; ks < 32; ks += 8) {
            uint32_t af[2][4];
            ldsmA(af[0], aS, 36, wm,      ks, lane);
            ldsmA(af[1], aS, 36, wm + 16, ks, lane);
#pragma unroll
            for (int nt = 0; nt < 8; nt += 2) {
                uint32_t bf[4];
                ldsmB4(bf, bS, 36, wn + nt * 8, ks, lane);
                mma_tf32(acc[0][nt],     af[0], bf);
                mma_tf32(acc[1][nt],     af[1], bf);
                mma_tf32(acc[0][nt + 1], af[0], bf + 2);
                mma_tf32(acc[1][nt + 1], af[1], bf + 2);
            }
        }
    }

    float* OUT = (rz == 0 ? D1 : rz == 1 ? D2 : rz == 2 ? D3 : D4)
                 + (size_t)h * LL * LL;
#pragma unroll
    for (int mt = 0; mt < 2; mt++) {
#pragma unroll
        for (int nt = 0; nt < 8; nt++) {
            int rg = i0 + wm + mt * 16 + (lane >> 2);
            int cg = j0 + wn + nt * 8 + (lane & 3) * 2;
#pragma unroll
            for (int half = 0; half < 2; half++) {
                int rw = rg + half * 8;
                float2 v = {0.125f * acc[mt][nt][half * 2 + 0],
                            0.125f * acc[mt][nt][half * 2 + 1]};
                *(float2*)&OUT[(size_t)rw * LL + cg] = v;
            }
        }
    }
}

// ---------------------------------------------------------------------------
// Column attention over fp16 QKVW. Staging converts half->float into SMEM.
// ---------------------------------------------------------------------------
__global__ __launch_bounds__(256, 2) void col_attn_tc(
    const __half* __restrict__ QKV, float* __restrict__ CWH)
{
    extern __shared__ float sm[];
    float* Qs = sm;
    float* Ks = sm + 128 * 68;
    float* P  = sm;
    float* Vt = sm + 2 * 128 * 68;

    const int l = blockIdx.x >> 3;
    const int h = blockIdx.x & 7;
    const int t = threadIdx.x;
    const int lane = t & 31;
    const int wid  = t >> 5;
    const int wm   = wid * 16;
    const int fr   = lane >> 2;
    const int q2   = (lane & 3) * 2;
    const size_t RS = (size_t)LL * LDW;        // stride in halves
    const uint32_t qsu = smem_u32(Qs);
    const uint32_t ksu = smem_u32(Ks);
    const uint32_t psu = smem_u32(P);
    const uint32_t vsu = smem_u32(Vt);

    const __half* qb = QKV + (size_t)l * LDW + h * DHEAD;
    const __half* kb = qb + 512;
    const __half* vb = qb + 1024;

    // stage Q, K: 128 rows x 64 halves = 1024 half8 chunks
    for (int idx = t; idx < 1024; idx += 256) {
        int row = idx >> 3, c8 = (idx & 7) * 8;
        uint4 ra = *(const uint4*)(qb + row * RS + c8);
        uint4 rb = *(const uint4*)(kb + row * RS + c8);
        const __half2* ha = (const __half2*)&ra;
        const __half2* hb = (const __half2*)&rb;
#pragma unroll
        for (int u = 0; u < 4; u++) {
            float2 fa = __half22float2(ha[u]);
            float2 fb = __half22float2(hb[u]);
            Qs[row * 68 + c8 + u * 2]     = fa.x;
            Qs[row * 68 + c8 + u * 2 + 1] = fa.y;
            Ks[row * 68 + c8 + u * 2]     = fb.x;
            Ks[row * 68 + c8 + u * 2 + 1] = fb.y;
        }
    }
    __syncthreads();

    float acc[16][4];
#pragma unroll
    for (int nt = 0; nt < 16; nt++)
#pragma unroll
        for (int i = 0; i < 4; i++) acc[nt][i] = 0.f;

#pragma unroll
    for (int ks = 0; ks < 64; ks += 8) {
        uint32_t af[4];
        ldsmA(af, qsu, 68, wm, ks, lane);
#pragma unroll
        for (int nt = 0; nt < 16; nt += 2) {
            uint32_t bf[4];
            ldsmB4(bf, ksu, 68, nt * 8, ks, lane);
            mma_tf32(acc[nt],     af, bf);
            mma_tf32(acc[nt + 1], af, bf + 2);
        }
    }

    float mx0 = -1e30f, mx1 = -1e30f;
#pragma unroll
    for (int nt = 0; nt < 16; nt++) {
        mx0 = fmaxf(mx0, fmaxf(acc[nt][0], acc[nt][1]));
        mx1 = fmaxf(mx1, fmaxf(acc[nt][2], acc[nt][3]));
    }
    mx0 = fmaxf(mx0, __shfl_xor_sync(0xffffffffu, mx0, 1));
    mx0 = fmaxf(mx0, __shfl_xor_sync(0xffffffffu, mx0, 2));
    mx1 = fmaxf(mx1, __shfl_xor_sync(0xffffffffu, mx1, 1));
    mx1 = fmaxf(mx1, __shfl_xor_sync(0xffffffffu, mx1, 2));
    float s0 = 0.f, s1 = 0.f;
#pragma unroll
    for (int nt = 0; nt < 16; nt++) {
        acc[nt][0] = __expf(0.125f * (acc[nt][0] - mx0)); s0 += acc[nt][0];
        acc[nt][1] = __expf(0.125f * (acc[nt][1] - mx0)); s0 += acc[nt][1];
        acc[nt][2] = __expf(0.125f * (acc[nt][2] - mx1)); s1 += acc[nt][2];
        acc[nt][3] = __expf(0.125f * (acc[nt][3] - mx1)); s1 += acc[nt][3];
    }
    s0 += __shfl_xor_sync(0xffffffffu, s0, 1);
    s0 += __shfl_xor_sync(0xffffffffu, s0, 2);
    s1 += __shfl_xor_sync(0xffffffffu, s1, 1);
    s1 += __shfl_xor_sync(0xffffffffu, s1, 2);

    __syncthreads();

#pragma unroll
    for (int nt = 0; nt < 16; nt++) {
        float2 p0 = {tf32f(acc[nt][0]), tf32f(acc[nt][1])};
        float2 p1 = {tf32f(acc[nt][2]), tf32f(acc[nt][3])};
        *(float2*)&P[(wm + fr) * 132 + nt * 8 + q2]     = p0;
        *(float2*)&P[(wm + fr + 8) * 132 + nt * 8 + q2] = p1;
    }
    // stage V transposed: read half8 rows, scatter to Vt[d][j]
    for (int idx = t; idx < 1024; idx += 256) {
        int j = idx >> 3, c8 = (idx & 7) * 8;
        uint4 rv = *(const uint4*)(vb + j * RS + c8);
        const __half2* hv = (const __half2*)&rv;
#pragma unroll
        for (int u = 0; u < 4; u++) {
            float2 f = __half22float2(hv[u]);
            Vt[(c8 + u * 2) * 132 + j]     = f.x;
            Vt[(c8 + u * 2 + 1) * 132 + j] = f.y;
        }
    }
    __syncthreads();

    float o[8][4];
#pragma unroll
    for (int nt = 0; nt < 8; nt++)
#pragma unroll
        for (int i = 0; i < 4; i++) o[nt][i] = 0.f;

#pragma unroll
    for (int ks = 0; ks < 128; ks += 8) {
        uint32_t af[4];
        ldsmA(af, psu, 132, wm, ks, lane);
#pragma unroll
        for (int nt = 0; nt < 8; nt += 2) {
            uint32_t bf[4];
            ldsmB4(bf, vsu, 132, nt * 8, ks, lane);
            mma_tf32(o[nt],     af, bf);
            mma_tf32(o[nt + 1], af, bf + 2);
        }
    }

    const float inv0 = 1.f / s0, inv1 = 1.f / s1;
    float* ow = CWH + (size_t)l * LDC2 + h * DHEAD;
    const size_t OS = (size_t)LL * LDC2;
#pragma unroll
    for (int nt = 0; nt < 8; nt++) {
        int cg = nt * 8 + q2;
        float2 v0 = {tf32f(o[nt][0] * inv0), tf32f(o[nt][1] * inv0)};
        float2 v1 = {tf32f(o[nt][2] * inv1), tf32f(o[nt][3] * inv1)};
        *(float2*)(ow + (size_t)(wm + fr) * OS + cg)     = v0;
        *(float2*)(ow + (size_t)(wm + fr + 8) * OS + cg) = v1;
    }
}

// ---------------------------------------------------------------------------
// oh_tc (unchanged)
// ---------------------------------------------------------------------------
__global__ __launch_bounds__(256) void oh_tc(
    const float* __restrict__ ATT, const float* __restrict__ QKV,
    float* __restrict__ CWH)
{
    __shared__ float As[128 * 20];
    __shared__ float Bs[64 * 20];

    const int t    = threadIdx.x;
    const int lane = t & 31;
    const int wid  = t >> 5;
    const int wm   = (wid & 3) * 32;
    const int wn   = (wid >> 2) * 32;
    const int i0 = blockIdx.x * 128;
    const int r  = blockIdx.y >> 3;
    const int h  = blockIdx.y & 7;
    const uint32_t asu = smem_u32(As);
    const uint32_t bsu = smem_u32(Bs);

    float acc[2][4][4];
#pragma unroll
    for (int mt = 0; mt < 2; mt++)
#pragma unroll
        for (int nt = 0; nt < 4; nt++)
#pragma unroll
            for (int i = 0; i < 4; i++) acc[mt][nt][i] = 0.f;

    for (int k0 = 0; k0 < LL; k0 += 16) {
#pragma unroll
        for (int i = 0; i < 2; i++) {
            int idx = t + 256 * i;
            int row = idx >> 2, c4 = (idx & 3) * 4;
            float4 va = *(const float4*)&ATT[((size_t)h * LL + i0 + row) * LL + k0 + c4];
            uint4 ua;
            ua.x = f2tf32(va.x); ua.y = f2tf32(va.y);
            ua.z = f2tf32(va.z); ua.w = f2tf32(va.w);
            *(uint4*)&As[row * 20 + c4] = ua;
        }
        {
            int kr = t >> 4;
            int dc = (t & 15) * 4;
            float4 vb = *(const float4*)&QKV[((size_t)(r * LL + k0 + kr)) * LDH + 1024 + h * DHEAD + dc];
            Bs[(dc + 0) * 20 + kr] = vb.x;
            Bs[(dc + 1) * 20 + kr] = vb.y;
            Bs[(dc + 2) * 20 + kr] = vb.z;
            Bs[(dc + 3) * 20 + kr] = vb.w;
        }
        __syncthreads();
#pragma unroll
        for (int ks = 0; ks < 16; ks += 8) {
            uint32_t af[2][4];
            ldsmA(af[0], asu, 20, wm,      ks, lane);
            ldsmA(af[1], asu, 20, wm + 16, ks, lane);
#pragma unroll
            for (int nt = 0; nt < 4; nt += 2) {
                uint32_t bf[4];
                ldsmB4(bf, bsu, 20, wn + nt * 8, ks, lane);
                mma_tf32(acc[0][nt],     af[0], bf);
                mma_tf32(acc[1][nt],     af[1], bf);
                mma_tf32(acc[0][nt + 1], af[0], bf + 2);
                mma_tf32(acc[1][nt + 1], af[1], bf + 2);
            }
        }
        __syncthreads();
    }

#pragma unroll
    for (int mt = 0; mt < 2; mt++) {
#pragma unroll
        for (int nt = 0; nt < 4; nt++) {
            int rloc = i0 + wm + mt * 16 + (lane >> 2);
            int cg   = wn + nt * 8 + (lane & 3) * 2;
#pragma unroll
            for (int half = 0; half < 2; half++) {
                int rw = rloc + half * 8;
                float2 v = {tf32f(acc[mt][nt][half * 2 + 0]),
                            tf32f(acc[mt][nt][half * 2 + 1])};
                *(float2*)&CWH[((size_t)(r * LL + rw)) * LDC2 + 512 + h * DHEAD + cg] = v;
            }
        }
    }
}

// ---------------------------------------------------------------------------
__global__ __launch_bounds__(128) void tie_k(
    const float* __restrict__ QS, const float* __restrict__ QKV,
    float* __restrict__ TIE)
{
    const int l = blockIdx.x >> 3;
    const int h = blockIdx.x & 7;
    const int r = threadIdx.x;
    const float* q = &QS[l * DDIM + h * DHW];
    const float* k = &QKV[((size_t)r * LL + l) * LDH + 1536 + h * DHW];
    float s = 0.f;
#pragma unroll
    for (int d = 0; d < DHW; d++) s += q[d] * k[d];
    s *= 0.25f;

    __shared__ float red[128];
    red[r] = s; __syncthreads();
    for (int o = 64; o; o >>= 1) { if (r < o) red[r] = fmaxf(red[r], red[r + o]); __syncthreads(); }
    float m = red[0]; __syncthreads();
    float e = __expf(s - m);
    red[r] = e; __syncthreads();
    for (int o = 64; o; o >>= 1) { if (r < o) red[r] += red[r + o]; __syncthreads(); }
    TIE[((size_t)h * RR + r) * LL + l] = e / red[0];
}

// ---------------------------------------------------------------------------
__global__ __launch_bounds__(128) void pb_k(
    const float* __restrict__ pair, const float* __restrict__ gam,
    const float* __restrict__ bet, const float* __restrict__ Wp,
    float* __restrict__ PB)
{
    const int w    = threadIdx.x >> 5;
    const int lane = threadIdx.x & 31;
    const int pid  = blockIdx.x * 4 + w;
    float4 x4 = *(const float4*)&pair[(size_t)pid * DPAIR + lane * 4];
    float x[4] = {x4.x, x4.y, x4.z, x4.w};
    float s1 = x[0] + x[1] + x[2] + x[3];
    float s2 = x[0]*x[0] + x[1]*x[1] + x[2]*x[2] + x[3]*x[3];
#pragma unroll
    for (int o = 16; o; o >>= 1) {
        s1 += __shfl_xor_sync(0xffffffffu, s1, o);
        s2 += __shfl_xor_sync(0xffffffffu, s2, o);
    }
    float mu  = s1 * (1.f / DPAIR);
    float var = s2 * (1.f / DPAIR) - mu * mu;
    float inv = rsqrtf(var + 1e-5f);

    float acc[8];
#pragma unroll
    for (int hh = 0; hh < 8; hh++) acc[hh] = 0.f;
#pragma unroll
    for (int u = 0; u < 4; u++) {
        int c = lane * 4 + u;
        float nx = (x[u] - mu) * inv * gam[c] + bet[c];
#pragma unroll
        for (int hh = 0; hh < 8; hh++) acc[hh] += nx * Wp[c * 8 + hh];
    }
#pragma unroll
    for (int o = 16; o; o >>= 1)
#pragma unroll
        for (int hh = 0; hh < 8; hh++) acc[hh] += __shfl_xor_sync(0xffffffffu, acc[hh], o);
    if (lane == 0) {
#pragma unroll
        for (int hh = 0; hh < 8; hh++) PB[(size_t)hh * LL * LL + pid] = acc[hh];
    }
}

// ---------------------------------------------------------------------------
__global__ __launch_bounds__(128) void softh_k(
    const float* __restrict__ D1, const float* __restrict__ D2,
    const float* __restrict__ D3, const float* __restrict__ D4,
    const float* __restrict__ PB, float* __restrict__ ATT)
{
    const int i = blockIdx.x;
    const int h = blockIdx.y;
    const int t = threadIdx.x;
    const size_t base = ((size_t)h * LL + i) * LL;
    const float* dp1 = D1 + base;
    const float* dp2 = D2 + base;
    const float* dp3 = D3 + base;
    const float* dp4 = D4 + base;
    const float* pb  = PB + base;
    float x[3];
#pragma unroll
    for (int u = 0; u < 3; u++) {
        int j = t + u * 128;
        x[u] = (dp1[j] + dp2[j]) + (dp3[j] + dp4[j]) + pb[j];
    }
    __shared__ float red[128];
    float lm = fmaxf(fmaxf(x[0], x[1]), x[2]);
    red[t] = lm; __syncthreads();
    for (int o = 64; o; o >>= 1) { if (t < o) red[t] = fmaxf(red[t], red[t + o]); __syncthreads(); }
    float mx = red[0]; __syncthreads();
    float e[3], ls = 0.f;
#pragma unroll
    for (int u = 0; u < 3; u++) { e[u] = __expf(x[u] - mx); ls += e[u]; }
    red[t] = ls; __syncthreads();
    for (int o = 64; o; o >>= 1) { if (t < o) red[t] += red[t + o]; __syncthreads(); }
    float inv = 1.f / red[0];
    float* ap = ATT + base;
#pragma unroll
    for (int u = 0; u < 3; u++) ap[t + u * 128] = e[u] * inv;
}

// ---------------------------------------------------------------------------
static void* symv(const void* s) {
    void* p = nullptr;
    cudaGetSymbolAddress(&p, s);
    return p;
}

extern "C" void kernel_launch(void* const* d_in, const int* in_sizes, int n_in,
                              void* d_out, int out_size)
{
    const float* m     = (const float*)d_in[0];
    const float* pair  = (const float*)d_in[1];
    const float* Wq_w  = (const float*)d_in[2];
    const float* Wkv_w = (const float*)d_in[3];
    const float* Wo_w  = (const float*)d_in[4];
    const float* bo_w  = (const float*)d_in[5];
    const float* Wq_h  = (const float*)d_in[6];
    const float* Wkv_h = (const float*)d_in[7];
    const float* Wo_h  = (const float*)d_in[8];
    const float* bo_h  = (const float*)d_in[9];
    const float* ln_g  = (const float*)d_in[10];
    const float* ln_b  = (const float*)d_in[11];
    const float* Wpair = (const float*)d_in[12];
    const float* Wsq   = (const float*)d_in[13];
    const float* bsq   = (const float*)d_in[14];
    const float* Wsk   = (const float*)d_in[15];
    const float* bsk   = (const float*)d_in[16];
    float* out = (float*)d_out;

    float*  Mt    = (float*)symv(g_Mt);
    __half* QKVW  = (__half*)symv(g_QKVW);
    float*  QKVH  = (float*)symv(g_QKVH);
    float*  QW    = (float*)symv(g_QW);
    float*  CWH   = (float*)symv(g_CWH);
    float*  QS    = (float*)symv(g_QS);
    float*  TIE   = (float*)symv(g_TIE);
    float*  DOTS1 = (float*)symv(g_DOTS1);
    float*  DOTS2 = (float*)symv(g_DOTS2);
    float*  DOTS3 = (float*)symv(g_DOTS3);
    float*  DOTS4 = (float*)symv(g_DOTS4);
    float*  PB    = (float*)symv(g_PB);
    float*  ATT   = (float*)symv(g_ATT);
    float*  WtW   = (float*)symv(g_WtW);
    float*  WtH   = (float*)symv(g_WtH);
    float*  WtO   = (float*)symv(g_WtO);
    float*  WtSq  = (float*)symv(g_WtSq);
    float*  BH    = (float*)symv(g_BH);

    const int CA_SMEM = (2 * 128 * 68 + 64 * 132) * 4;
    cudaFuncSetAttribute(col_attn_tc, cudaFuncAttributeMaxDynamicSharedMemorySize, CA_SMEM);
    cudaFuncSetAttribute(gemm_tc, cudaFuncAttributeMaxDynamicSharedMemorySize, GEMM_SMEM);
    cudaFuncSetAttribute(dots_tc, cudaFuncAttributeMaxDynamicSharedMemorySize, DOTS_SMEM);

    static cudaStream_t sB = nullptr, sC = nullptr;
    static cudaEvent_t evMt, evPB, evB, evC;
    if (sB == nullptr) {
        cudaStreamCreateWithFlags(&sB, cudaStreamNonBlocking);
        cudaStreamCreateWithFlags(&sC, cudaStreamNonBlocking);
        cudaEventCreateWithFlags(&evMt, cudaEventDisableTiming);
        cudaEventCreateWithFlags(&evPB, cudaEventDisableTiming);
        cudaEventCreateWithFlags(&evB,  cudaEventDisableTiming);
        cudaEventCreateWithFlags(&evC,  cudaEventDisableTiming);
    }

    const dim3 tb(32, 8);

    // ---- stream 0: width path (#4 = ncu capture slot = col_attn_tc) ----
    cvt_k<<<ML * DDIM / 1024, 256>>>(m, Mt);                                   // #1
    cudaEventRecord(evMt, 0);
    transpose2_k<<<dim3(48, 4), tb>>>(Wq_w, INNERD, Wkv_w, 2 * INNERD, WtW);   // #2
    gemm_tc<<<dim3(12, 384), 256, GEMM_SMEM>>>(Mt, DDIM, WtW, DDIM, nullptr, nullptr,
                                               nullptr, QKVW, LDW, DDIM, 1.f); // #3 (fp16 out)
    col_attn_tc<<<LL * HHEADS, 256, CA_SMEM>>>(QKVW, CWH);                     // #4 (ncu)

    // ---- stream B: height path ----
    cudaStreamWaitEvent(sB, evMt, 0);
    transpose2_k<<<dim3(48, 4), tb, 0, sB>>>(Wq_h, INNERD, Wkv_h, 2 * INNERD, WtH);
    transpose_k<<<dim3(4, 4),  tb, 0, sB>>>(Wsk,   WtH + 1536 * DDIM, DDIM, DDIM);
    transpose_k<<<dim3(4, 4),  tb, 0, sB>>>(Wsq,   WtSq,              DDIM, DDIM);
    biasext_k<<<(LDH + 255) / 256, 256, 0, sB>>>(bsk, BH);
    gemm_tc<<<dim3(13, 384), 256, GEMM_SMEM, sB>>>(Mt, DDIM, WtH, DDIM, BH, nullptr,
                                                   QKVH, nullptr, LDH, DDIM, 1.f);
    gemm_tc<<<dim3(1, 3), 256, GEMM_SMEM, sB>>>(Mt, DDIM, WtSq, DDIM, bsq, nullptr,
                                                QS, nullptr, DDIM, DDIM, 1.f);
    tie_k<<<LL * HHEADS, 128, 0, sB>>>(QS, QKVH, TIE);
    scaleq_k<<<dim3(LL, RR), 128, 0, sB>>>(TIE, QKVH, QW);
    dots_tc<<<dim3(3, 3, 32), 256, DOTS_SMEM, sB>>>(QW, QKVH,
                                                    DOTS1, DOTS2, DOTS3, DOTS4);

    // ---- stream C: pair bias + output-weight prep ----
    cudaStreamWaitEvent(sC, evMt, 0);
    pb_k<<<LL * LL / 4, 128, 0, sC>>>(pair, ln_g, ln_b, Wpair, PB);
    cudaEventRecord(evPB, sC);
    transpose_k<<<dim3(4, 16), tb, 0, sC>>>(Wo_w, WtO,       DDIM, LDC2);
    transpose_k<<<dim3(4, 16), tb, 0, sC>>>(Wo_h, WtO + 512, DDIM, LDC2);
    cudaEventRecord(evC, sC);

    // ---- stream B tail ----
    cudaStreamWaitEvent(sB, evPB, 0);
    softh_k<<<dim3(LL, HHEADS), 128, 0, sB>>>(DOTS1, DOTS2, DOTS3, DOTS4, PB, ATT);
    oh_tc<<<dim3(3, RR * HHEADS), 256, 0, sB>>>(ATT, QKVH, CWH);
    cudaEventRecord(evB, sB);

    // ---- join: fused output GEMM ----
    cudaStreamWaitEvent(0, evB, 0);
    cudaStreamWaitEvent(0, evC, 0);
    gemm_tc<<<dim3(1, 384), 256, GEMM_SMEM>>>(CWH, LDC2, WtO, LDC2, bo_w, bo_h,
                                              out, nullptr, DDIM, LDC2, 0.5f);
}